// round 5
// baseline (speedup 1.0000x reference)
#include <cuda_runtime.h>
#include <math.h>
#include <stdint.h>

#define B_    4
#define NQ_   1024
#define NKV_  2048
#define D_    288

__device__ constexpr int   GRADEA[16] = {0,1,1,1,1,2,2,2,2,2,2,3,3,3,3,4};
__device__ constexpr float METRICA[16] = {1.f,1.f,-1.f,-1.f,-1.f,-1.f,-1.f,-1.f,
                                          1.f,1.f, 1.f, 1.f, 1.f, 1.f,-1.f,-1.f};
__constant__ int GRADE_RT[16] = {0,1,1,1,1,2,2,2,2,2,2,3,3,3,3,4};

// scratch
__device__ float QB[(size_t)B_*8*NQ_*D_];
__device__ float KB[(size_t)B_*8*NKV_*D_];
__device__ float VB[(size_t)B_*8*NKV_*D_];
__device__ float OB[(size_t)B_*NQ_*8*D_];
// fragment-major operand buffers
__device__ float QF[(size_t)32*16*18432];   // [bh][qtile][mtile4][ds36][lane32][4]
__device__ float KF[(size_t)32*32*18432];   // [bh][ktile][chunk3][n8][dsl12][lane32][2]
__device__ float VF[(size_t)32*32*18432];   // [bh][ktile][chunk3][ks8][ntl12][lane32][2]

__device__ __forceinline__ float tf32f(float x) {
    uint32_t r; asm("cvt.rna.tf32.f32 %0,%1;" : "=r"(r) : "f"(x));
    return __uint_as_float(r);
}
#define MMA(c,a0,a1,a2,a3,b0,b1) \
    asm volatile("mma.sync.aligned.m16n8k8.row.col.f32.tf32.tf32.f32 " \
        "{%0,%1,%2,%3},{%4,%5,%6,%7},{%8,%9},{%0,%1,%2,%3};" \
        : "+f"((c)[0]),"+f"((c)[1]),"+f"((c)[2]),"+f"((c)[3]) \
        : "r"(a0),"r"(a1),"r"(a2),"r"(a3),"r"(b0),"r"(b1))

__device__ __forceinline__ void cp16(uint32_t dst, const float* src) {
    asm volatile("cp.async.ca.shared.global [%0],[%1],16;" :: "r"(dst), "l"(src));
}
#define CPCOMMIT() asm volatile("cp.async.commit_group;")
#define CPWAIT(n)  asm volatile("cp.async.wait_group %0;" :: "n"(n))

// ============================================================================
// QKV projection (one token per block, 128 threads) — unchanged.
// ============================================================================
__global__ void proj_kernel(const float* __restrict__ x_mv, const float* __restrict__ x_s,
                            const float* __restrict__ w_mv, const float* __restrict__ w_s2mv,
                            const float* __restrict__ w_mvs2s, const float* __restrict__ w_s2s,
                            const float* __restrict__ b_mv, const float* __restrict__ b_s,
                            int ntok, int dst, int applyMetric)
{
    __shared__ float xmv[256];
    __shared__ float xs[32];
    const int t = blockIdx.x, b = t / ntok, n = t % ntok, tid = threadIdx.x;

    const float* xp = x_mv + (size_t)t * 256;
    xmv[tid] = xp[tid]; xmv[tid + 128] = xp[tid + 128];
    if (tid < 32) xs[tid] = x_s[(size_t)t * 32 + tid];
    __syncthreads();

    float* out = (dst == 0) ? QB : (dst == 1) ? KB : VB;
    {
        const int o = tid;
        const float* wr = w_mv + o * 80;
        float y[16];
#pragma unroll
        for (int x = 0; x < 16; ++x) {
            float acc = 0.f;
#pragma unroll
            for (int i = 0; i < 16; ++i) acc += xmv[i * 16 + x] * wr[i * 5 + GRADEA[x]];
            y[x] = acc;
        }
        float a0 = b_mv[o];
        const float* ws = w_s2mv + o * 32;
#pragma unroll
        for (int s = 0; s < 32; ++s) a0 += xs[s] * ws[s];
        y[0] += a0;
        const int head = o & 7, hid = o >> 3;
        float* op = out + ((size_t)(b * 8 + head) * ntok + n) * D_ + hid * 16;
#pragma unroll
        for (int x = 0; x < 16; ++x) op[x] = applyMetric ? y[x] * METRICA[x] : y[x];
    }
#pragma unroll
    for (int rr = 0; rr < 2; ++rr) {
        const int o = tid * 2 + rr;
        float y = b_s[o];
        const float* wm = w_mvs2s + o * 16;
#pragma unroll
        for (int i = 0; i < 16; ++i) y += xmv[i * 16] * wm[i];
        const float* ws = w_s2s + o * 32;
#pragma unroll
        for (int s = 0; s < 32; ++s) y += xs[s] * ws[s];
        const int head = o & 7, hid = o >> 3;
        out[((size_t)(b * 8 + head) * ntok + n) * D_ + 256 + hid] = y;
    }
}

// ============================================================================
// Repack kernels (256 threads): stage 64x288 tile, emit fragment-major.
// ============================================================================
#define STG_STRIDE 292
__global__ void repackQ_kernel()
{
    extern __shared__ float ss[];
    const int qt = blockIdx.x, bh = blockIdx.y, tid = threadIdx.x;
    const float SCALE = 0.0589255650988789f;  // 1/sqrt(288) folded into Q
    const float* src = QB + ((size_t)bh * NQ_ + qt * 64) * D_;
#pragma unroll
    for (int i = 0; i < 18; ++i) {
        int idx = i * 256 + tid, row = idx / 72, c4 = idx % 72;
        float4 v = *(const float4*)(src + (size_t)row * D_ + c4 * 4);
        float* d = ss + row * STG_STRIDE + c4 * 4;
        d[0] = v.x; d[1] = v.y; d[2] = v.z; d[3] = v.w;
    }
    __syncthreads();
    float* dst = QF + (size_t)(bh * 16 + qt) * 18432;
#pragma unroll
    for (int i = 0; i < 18; ++i) {
        int e = i * 256 + tid;
        int m = e / 1152, rem = e % 1152, ds = rem >> 5, lane = rem & 31;
        int g = lane >> 2, t = lane & 3;
        int r0 = m * 16 + g, c0 = ds * 8 + t;
        float4 v;
        v.x = tf32f(ss[r0 * STG_STRIDE + c0] * SCALE);
        v.y = tf32f(ss[(r0 + 8) * STG_STRIDE + c0] * SCALE);
        v.z = tf32f(ss[r0 * STG_STRIDE + c0 + 4] * SCALE);
        v.w = tf32f(ss[(r0 + 8) * STG_STRIDE + c0 + 4] * SCALE);
        *(float4*)(dst + (size_t)e * 4) = v;
    }
}

__global__ void repackK_kernel()
{
    extern __shared__ float ss[];
    const int kt = blockIdx.x, bh = blockIdx.y, tid = threadIdx.x;
    const float* src = KB + ((size_t)bh * NKV_ + kt * 64) * D_;
#pragma unroll
    for (int i = 0; i < 18; ++i) {
        int idx = i * 256 + tid, row = idx / 72, c4 = idx % 72;
        float4 v = *(const float4*)(src + (size_t)row * D_ + c4 * 4);
        float* d = ss + row * STG_STRIDE + c4 * 4;
        d[0] = v.x; d[1] = v.y; d[2] = v.z; d[3] = v.w;
    }
    __syncthreads();
    float* dst = KF + (size_t)(bh * 32 + kt) * 18432;
#pragma unroll
    for (int i = 0; i < 36; ++i) {
        int e = i * 256 + tid;
        int lane = e & 31, tmp = e >> 5;
        int dsl = tmp % 12; tmp /= 12;
        int n = tmp & 7, chunk = tmp >> 3;
        int g = lane >> 2, t = lane & 3;
        int row = n * 8 + g, col = (chunk * 12 + dsl) * 8 + t;
        float2 v = { tf32f(ss[row * STG_STRIDE + col]),
                     tf32f(ss[row * STG_STRIDE + col + 4]) };
        *(float2*)(dst + (size_t)e * 2) = v;
    }
}

__global__ void repackV_kernel()
{
    extern __shared__ float ss[];
    const int kt = blockIdx.x, bh = blockIdx.y, tid = threadIdx.x;
    const float* src = VB + ((size_t)bh * NKV_ + kt * 64) * D_;
#pragma unroll
    for (int i = 0; i < 18; ++i) {
        int idx = i * 256 + tid, row = idx / 72, c4 = idx % 72;
        float4 v = *(const float4*)(src + (size_t)row * D_ + c4 * 4);
        float* d = ss + row * STG_STRIDE + c4 * 4;
        d[0] = v.x; d[1] = v.y; d[2] = v.z; d[3] = v.w;
    }
    __syncthreads();
    float* dst = VF + (size_t)(bh * 32 + kt) * 18432;
#pragma unroll
    for (int i = 0; i < 36; ++i) {
        int e = i * 256 + tid;
        int lane = e & 31, tmp = e >> 5;
        int ntl = tmp % 12; tmp /= 12;
        int ks = tmp & 7, chunk = tmp >> 3;
        int g = lane >> 2, t = lane & 3;
        int col = chunk * 96 + ntl * 8 + g, row0 = ks * 8 + t;
        float2 v = { tf32f(ss[row0 * STG_STRIDE + col]),
                     tf32f(ss[(row0 + 4) * STG_STRIDE + col]) };
        *(float2*)(dst + (size_t)e * 2) = v;
    }
}

// ============================================================================
// Flash attention: 512 threads (16 warps, 4/SMSP), 3-buffer 96d-chunk ring.
// grid=(16,32).
// ============================================================================
#define QS_OFF   0
#define BUF_OFF  18432
#define CHUNK_F  6144
#define PS_OFF   36864
#define RED_OFF  41216
#define MR_OFF   41728
#define LR_OFF   41792
#define AR_OFF   41856
#define SMF      41920
#define PSTR 68

__device__ __forceinline__ void ldchunk(float* smbuf, const float* gsrc, int tid)
{
    uint32_t s0 = (uint32_t)__cvta_generic_to_shared(smbuf);
#pragma unroll
    for (int i = 0; i < 3; ++i) {
        int o = (i * 512 + tid) * 4;
        cp16(s0 + o * 4, gsrc + o);
    }
}

__device__ __forceinline__ void scores_chunk(const float* Qs, const float* buf,
                                             float cS[2][4], int c, int wqS, int wkS, int lane)
{
#pragma unroll
    for (int dsl = 0; dsl < 12; ++dsl) {
        float4 A = *(const float4*)(Qs + ((wqS * 36 + c * 12 + dsl) * 32 + lane) * 4);
        float2 B0 = *(const float2*)(buf + (((2 * wkS) * 12 + dsl) * 32 + lane) * 2);
        float2 B1 = *(const float2*)(buf + (((2 * wkS + 1) * 12 + dsl) * 32 + lane) * 2);
        uint32_t a0 = __float_as_uint(A.x), a1 = __float_as_uint(A.y),
                 a2 = __float_as_uint(A.z), a3 = __float_as_uint(A.w);
        MMA(cS[0], a0, a1, a2, a3, __float_as_uint(B0.x), __float_as_uint(B0.y));
        MMA(cS[1], a0, a1, a2, a3, __float_as_uint(B1.x), __float_as_uint(B1.y));
    }
}

__device__ __forceinline__ void pv_chunk(const float* Ps, const float* buf,
                                         float O[3][4], int wqP, int wdP, int g, int t, int lane)
{
#pragma unroll
    for (int ks = 0; ks < 8; ++ks) {
        const float* pb = Ps + (wqP * 16 + g) * PSTR + ks * 8 + t;
        uint32_t a0 = __float_as_uint(pb[0]);
        uint32_t a1 = __float_as_uint(pb[8 * PSTR]);
        uint32_t a2 = __float_as_uint(pb[4]);
        uint32_t a3 = __float_as_uint(pb[8 * PSTR + 4]);
#pragma unroll
        for (int j = 0; j < 3; ++j) {
            float2 Bv = *(const float2*)(buf + ((ks * 12 + wdP * 3 + j) * 32 + lane) * 2);
            MMA(O[j], a0, a1, a2, a3, __float_as_uint(Bv.x), __float_as_uint(Bv.y));
        }
    }
}

__global__ __launch_bounds__(512, 1) void attn4_kernel()
{
    extern __shared__ float sm[];
    float* Qs   = sm + QS_OFF;
    float* buf0 = sm + BUF_OFF;
    float* buf1 = buf0 + CHUNK_F;
    float* buf2 = buf1 + CHUNK_F;
    float* Ps   = sm + PS_OFF;
    float* red  = sm + RED_OFF;
    float* mrow = sm + MR_OFF;
    float* lrow = sm + LR_OFF;
    float* arow = sm + AR_OFF;

    const int tid = threadIdx.x, bh = blockIdx.y, qt = blockIdx.x;
    const int w = tid >> 5, lane = tid & 31, g = lane >> 2, t = lane & 3;
    const int wqS = w & 3, wkS = w >> 2;     // scores: 16q x 16k per warp
    const int wqP = w & 3, wdP = w >> 2;     // PV: 16q x 24d per warp
    const int r = tid >> 3, seg = tid & 7;   // softmax: 8 threads / row

    const float* KFb = KF + (size_t)(bh * 32) * 18432;
    const float* VFb = VF + (size_t)(bh * 32) * 18432;

    // prefetch K(kt=0) chunks 0..2
    ldchunk(buf0, KFb, tid); CPCOMMIT();
    ldchunk(buf1, KFb + CHUNK_F, tid); CPCOMMIT();
    ldchunk(buf2, KFb + 2 * CHUNK_F, tid); CPCOMMIT();

    // load Q fragments
    {
        const float4* qsrc = (const float4*)(QF + (size_t)(bh * 16 + qt) * 18432);
        float4* qdst = (float4*)Qs;
#pragma unroll
        for (int i = 0; i < 9; ++i) qdst[i * 512 + tid] = qsrc[i * 512 + tid];
    }
    if (tid < 64) { mrow[tid] = -1e30f; lrow[tid] = 0.f; }

    float O[3][3][4];
#pragma unroll
    for (int c = 0; c < 3; ++c)
#pragma unroll
        for (int j = 0; j < 3; ++j)
#pragma unroll
            for (int k = 0; k < 4; ++k) O[c][j][k] = 0.f;

    for (int kt = 0; kt < 32; ++kt) {
        const int ktn = (kt + 1) & 31;           // last iter re-loads kt0 (harmless)
        const float* KFt = KFb + (size_t)kt * 18432;
        const float* KFn = KFb + (size_t)ktn * 18432;
        const float* VFt = VFb + (size_t)kt * 18432;

        float cS[2][4];
#pragma unroll
        for (int nt = 0; nt < 2; ++nt)
#pragma unroll
            for (int k = 0; k < 4; ++k) cS[nt][k] = 0.f;

        CPWAIT(2); __syncthreads();                       // K c0 ready
        scores_chunk(Qs, buf0, cS, 0, wqS, wkS, lane);
        CPWAIT(1); __syncthreads();                       // K c1 ready, b0 consumed
        ldchunk(buf0, VFt, tid); CPCOMMIT();              // V c0 -> b0
        scores_chunk(Qs, buf1, cS, 1, wqS, wkS, lane);
        CPWAIT(1); __syncthreads();                       // K c2 ready, b1 consumed
        ldchunk(buf1, VFt + CHUNK_F, tid); CPCOMMIT();    // V c1 -> b1
        scores_chunk(Qs, buf2, cS, 2, wqS, wkS, lane);

        // write raw scores
#pragma unroll
        for (int nt = 0; nt < 2; ++nt) {
            int row = wqS * 16 + g, col = wkS * 16 + nt * 8 + 2 * t;
            *(float2*)(Ps + row * PSTR + col) = make_float2(cS[nt][0], cS[nt][1]);
            *(float2*)(Ps + (row + 8) * PSTR + col) = make_float2(cS[nt][2], cS[nt][3]);
        }
        __syncthreads();                                  // scores done, b2 consumed
        ldchunk(buf2, VFt + 2 * CHUNK_F, tid); CPCOMMIT();// V c2 -> b2

        // softmax pass 1: partial maxima (8 threads / row)
        {
            float lm = -1e30f;
            const float* pr = Ps + r * PSTR + seg * 8;
#pragma unroll
            for (int j = 0; j < 8; ++j) lm = fmaxf(lm, pr[j]);
            red[tid] = lm;
        }
        __syncthreads();
        if (tid < 64) {
            float m8 = red[8 * tid];
#pragma unroll
            for (int j = 1; j < 8; ++j) m8 = fmaxf(m8, red[8 * tid + j]);
            float mo = mrow[tid], mn = fmaxf(mo, m8);
            mrow[tid] = mn; arow[tid] = __expf(mo - mn);
        }
        __syncthreads();
        // pass 2: exponentiate (tf32) + partial sums; rescale O in parallel
        {
            float mn = mrow[r], s = 0.f;
            float* pw = Ps + r * PSTR + seg * 8;
#pragma unroll
            for (int j = 0; j < 8; ++j) {
                float p = __expf(pw[j] - mn);
                pw[j] = tf32f(p); s += p;
            }
            red[tid] = s;
        }
        {
            float al0 = arow[wqP * 16 + g], al1 = arow[wqP * 16 + 8 + g];
#pragma unroll
            for (int c = 0; c < 3; ++c)
#pragma unroll
                for (int j = 0; j < 3; ++j) {
                    O[c][j][0] *= al0; O[c][j][1] *= al0;
                    O[c][j][2] *= al1; O[c][j][3] *= al1;
                }
        }
        __syncthreads();
        if (tid < 64) {
            float s8 = 0.f;
#pragma unroll
            for (int j = 0; j < 8; ++j) s8 += red[8 * tid + j];
            lrow[tid] = lrow[tid] * arow[tid] + s8;
        }

        CPWAIT(2); __syncthreads();                       // V c0 ready (+Ps final)
        pv_chunk(Ps, buf0, O[0], wqP, wdP, g, t, lane);
        CPWAIT(1); __syncthreads();                       // V c1 ready, b0 consumed
        ldchunk(buf0, KFn, tid); CPCOMMIT();              // next K c0
        pv_chunk(Ps, buf1, O[1], wqP, wdP, g, t, lane);
        CPWAIT(1); __syncthreads();                       // V c2 ready, b1 consumed
        ldchunk(buf1, KFn + CHUNK_F, tid); CPCOMMIT();    // next K c1
        pv_chunk(Ps, buf2, O[2], wqP, wdP, g, t, lane);
        __syncthreads();                                  // b2 consumed
        ldchunk(buf2, KFn + 2 * CHUNK_F, tid); CPCOMMIT();// next K c2
    }

    CPWAIT(0); __syncthreads();
    const float li0 = 1.f / lrow[wqP * 16 + g];
    const float li1 = 1.f / lrow[wqP * 16 + 8 + g];
    const int b = bh >> 3, hh = bh & 7;
    const int q0 = qt * 64 + wqP * 16 + g;
#pragma unroll
    for (int c = 0; c < 3; ++c)
#pragma unroll
        for (int j = 0; j < 3; ++j) {
            int d = c * 96 + (wdP * 3 + j) * 8 + 2 * t;
            size_t o0 = (((size_t)(b * NQ_ + q0)) * 8 + hh) * D_ + d;
            size_t o1 = (((size_t)(b * NQ_ + q0 + 8)) * 8 + hh) * D_ + d;
            *(float2*)(OB + o0) = make_float2(O[c][j][0] * li0, O[c][j][1] * li0);
            *(float2*)(OB + o1) = make_float2(O[c][j][2] * li1, O[c][j][3] * li1);
        }
}

// ============================================================================
// Output projection — unchanged.
// ============================================================================
__global__ void outproj_kernel(const float* __restrict__ wo_mv, const float* __restrict__ wo_s2mv,
                               const float* __restrict__ wo_mvs2s, const float* __restrict__ wo_s2s,
                               const float* __restrict__ bo_mv, const float* __restrict__ bo_s,
                               float* __restrict__ d_out)
{
    __shared__ float xm[2048];
    __shared__ float xsc[256];
    const int t = blockIdx.x, tid = threadIdx.x;
    const float* ob = OB + (size_t)t * 8 * D_;

    for (int idx = tid; idx < 2048; idx += 256) {
        const int c = idx >> 4, x = idx & 15, head = c >> 4, hid = c & 15;
        xm[idx] = ob[head * D_ + hid * 16 + x];
    }
    {
        const int head = tid >> 5, hid = tid & 31;
        xsc[tid] = ob[head * D_ + 256 + hid];
    }
    __syncthreads();
    {
        const int o = tid >> 4, x = tid & 15, gg = GRADE_RT[x];
        const float* wmx = wo_mv + (size_t)o * 128 * 5 + gg;
        float y = 0.f;
#pragma unroll 8
        for (int i = 0; i < 128; ++i) y += xm[i * 16 + x] * wmx[i * 5];
        if (x == 0) {
            float a = bo_mv[o];
            const float* ws = wo_s2mv + o * 256;
#pragma unroll 8
            for (int s = 0; s < 256; ++s) a += xsc[s] * ws[s];
            y += a;
        }
        d_out[(size_t)t * 256 + o * 16 + x] = y;
    }
    if (tid < 32) {
        const int o = tid;
        float y = bo_s[o];
        const float* wm = wo_mvs2s + o * 128;
#pragma unroll 8
        for (int i = 0; i < 128; ++i) y += xm[i * 16] * wm[i];
        const float* ws = wo_s2s + o * 256;
#pragma unroll 8
        for (int s = 0; s < 256; ++s) y += xsc[s] * ws[s];
        d_out[(size_t)B_ * NQ_ * 256 + (size_t)t * 32 + o] = y;
    }
}

extern "C" void kernel_launch(void* const* d_in, const int* in_sizes, int n_in,
                              void* d_out, int out_size)
{
    (void)in_sizes; (void)n_in; (void)out_size;
    const float* mv_kv = (const float*)d_in[0];
    const float* mv_q  = (const float*)d_in[1];
    const float* s_kv  = (const float*)d_in[2];
    const float* s_q   = (const float*)d_in[3];
    const float* wq_mv = (const float*)d_in[4],  *wq_s2mv = (const float*)d_in[5];
    const float* wq_m2s = (const float*)d_in[6], *wq_s2s = (const float*)d_in[7];
    const float* bq_mv = (const float*)d_in[8],  *bq_s = (const float*)d_in[9];
    const float* wk_mv = (const float*)d_in[10], *wk_s2mv = (const float*)d_in[11];
    const float* wk_m2s = (const float*)d_in[12],*wk_s2s = (const float*)d_in[13];
    const float* bk_mv = (const float*)d_in[14], *bk_s = (const float*)d_in[15];
    const float* wv_mv = (const float*)d_in[16], *wv_s2mv = (const float*)d_in[17];
    const float* wv_m2s = (const float*)d_in[18],*wv_s2s = (const float*)d_in[19];
    const float* bv_mv = (const float*)d_in[20], *bv_s = (const float*)d_in[21];
    const float* wo_mv = (const float*)d_in[22], *wo_s2mv = (const float*)d_in[23];
    const float* wo_m2s = (const float*)d_in[24],*wo_s2s = (const float*)d_in[25];
    const float* bo_mv = (const float*)d_in[26], *bo_s = (const float*)d_in[27];

    const int stage_smem = 64 * STG_STRIDE * sizeof(float);
    cudaFuncSetAttribute(repackQ_kernel, cudaFuncAttributeMaxDynamicSharedMemorySize, stage_smem);
    cudaFuncSetAttribute(repackK_kernel, cudaFuncAttributeMaxDynamicSharedMemorySize, stage_smem);
    cudaFuncSetAttribute(repackV_kernel, cudaFuncAttributeMaxDynamicSharedMemorySize, stage_smem);
    const int attn_smem = SMF * sizeof(float);                // 167,680 B
    cudaFuncSetAttribute(attn4_kernel, cudaFuncAttributeMaxDynamicSharedMemorySize, attn_smem);

    proj_kernel<<<B_ * NQ_, 128>>>(mv_q, s_q, wq_mv, wq_s2mv, wq_m2s, wq_s2s, bq_mv, bq_s, NQ_, 0, 0);
    proj_kernel<<<B_ * NKV_, 128>>>(mv_kv, s_kv, wk_mv, wk_s2mv, wk_m2s, wk_s2s, bk_mv, bk_s, NKV_, 1, 1);
    proj_kernel<<<B_ * NKV_, 128>>>(mv_kv, s_kv, wv_mv, wv_s2mv, wv_m2s, wv_s2s, bv_mv, bv_s, NKV_, 2, 0);

    repackQ_kernel<<<dim3(16, 32), 256, stage_smem>>>();
    repackK_kernel<<<dim3(32, 32), 256, stage_smem>>>();
    repackV_kernel<<<dim3(32, 32), 256, stage_smem>>>();

    attn4_kernel<<<dim3(16, 32), 512, attn_smem>>>();

    outproj_kernel<<<B_ * NQ_, 256>>>(wo_mv, wo_s2mv, wo_m2s, wo_s2s, bo_mv, bo_s, (float*)d_out);
}

// round 7
// speedup vs baseline: 1.0700x; 1.0700x over previous
#include <cuda_runtime.h>
#include <math.h>
#include <stdint.h>

#define B_    4
#define NQ_   1024
#define NKV_  2048
#define D_    288

__device__ constexpr int   GRADEA[16] = {0,1,1,1,1,2,2,2,2,2,2,3,3,3,3,4};
__device__ constexpr float METRICA[16] = {1.f,1.f,-1.f,-1.f,-1.f,-1.f,-1.f,-1.f,
                                          1.f,1.f, 1.f, 1.f, 1.f, 1.f,-1.f,-1.f};
__constant__ int GRADE_RT[16] = {0,1,1,1,1,2,2,2,2,2,2,3,3,3,3,4};

// scratch
__device__ __align__(1024) float QB[(size_t)B_*8*NQ_*D_];
__device__ __align__(1024) float KB[(size_t)B_*8*NKV_*D_];
__device__ __align__(1024) float VB[(size_t)B_*8*NKV_*D_];
__device__ __align__(1024) float OB[(size_t)B_*NQ_*8*D_];
// fragment-major operand buffers (same layouts as R5)
__device__ __align__(1024) float QF[(size_t)32*16*18432];   // [bh][qtile][mtile4][ds36][lane32][4]
__device__ __align__(1024) float KF[(size_t)32*32*18432];   // [bh][ktile][chunk3][n8][dsl12][lane32][2]
__device__ __align__(1024) float VF[(size_t)32*32*18432];   // [bh][ktile][chunk3][ks8][ntl12][lane32][2]

__device__ __forceinline__ float tf32f(float x) {
    uint32_t r; asm("cvt.rna.tf32.f32 %0,%1;" : "=r"(r) : "f"(x));
    return __uint_as_float(r);
}
#define MMA(c,a0,a1,a2,a3,b0,b1) \
    asm volatile("mma.sync.aligned.m16n8k8.row.col.f32.tf32.tf32.f32 " \
        "{%0,%1,%2,%3},{%4,%5,%6,%7},{%8,%9},{%0,%1,%2,%3};" \
        : "+f"((c)[0]),"+f"((c)[1]),"+f"((c)[2]),"+f"((c)[3]) \
        : "r"(a0),"r"(a1),"r"(a2),"r"(a3),"r"(b0),"r"(b1))

__device__ __forceinline__ uint32_t smem_u32(const void* p) {
    uint32_t a;
    asm("{ .reg .u64 t; cvta.to.shared.u64 t, %1; cvt.u32.u64 %0, t; }" : "=r"(a) : "l"(p));
    return a;
}
// ---- bulk async copy (sm_90 base feature) ----
__device__ __forceinline__ void bulkld(uint32_t sdst, const float* gsrc, uint32_t mbar, uint32_t bytes) {
    asm volatile("cp.async.bulk.shared::cluster.global.mbarrier::complete_tx::bytes [%0], [%1], %2, [%3];"
        :: "r"(sdst), "l"(gsrc), "r"(bytes), "r"(mbar) : "memory");
}
#define MB_INIT(mb, c)    asm volatile("mbarrier.init.shared.b64 [%0], %1;" :: "r"(mb), "r"(c) : "memory")
#define MB_EXPECT(mb, nb) asm volatile("mbarrier.arrive.expect_tx.shared.b64 _, [%0], %1;" :: "r"(mb), "r"(nb) : "memory")
#define MB_WAIT(mb, par) do { \
    asm volatile("{\n\t.reg .pred P1;\n\tWL_%=:\n\t" \
        "mbarrier.try_wait.parity.acquire.cta.shared::cta.b64 P1, [%0], %1, 0x989680;\n\t" \
        "@P1 bra.uni WD_%=;\n\tbra.uni WL_%=;\n\tWD_%=:\n\t}" \
        :: "r"(mb), "r"(par) : "memory"); } while (0)

// ============================================================================
// QKV projection (unchanged).
// ============================================================================
__global__ void proj_kernel(const float* __restrict__ x_mv, const float* __restrict__ x_s,
                            const float* __restrict__ w_mv, const float* __restrict__ w_s2mv,
                            const float* __restrict__ w_mvs2s, const float* __restrict__ w_s2s,
                            const float* __restrict__ b_mv, const float* __restrict__ b_s,
                            int ntok, int dst, int applyMetric)
{
    __shared__ float xmv[256];
    __shared__ float xs[32];
    const int t = blockIdx.x, b = t / ntok, n = t % ntok, tid = threadIdx.x;
    const float* xp = x_mv + (size_t)t * 256;
    xmv[tid] = xp[tid]; xmv[tid + 128] = xp[tid + 128];
    if (tid < 32) xs[tid] = x_s[(size_t)t * 32 + tid];
    __syncthreads();
    float* out = (dst == 0) ? QB : (dst == 1) ? KB : VB;
    {
        const int o = tid;
        const float* wr = w_mv + o * 80;
        float y[16];
#pragma unroll
        for (int x = 0; x < 16; ++x) {
            float acc = 0.f;
#pragma unroll
            for (int i = 0; i < 16; ++i) acc += xmv[i * 16 + x] * wr[i * 5 + GRADEA[x]];
            y[x] = acc;
        }
        float a0 = b_mv[o];
        const float* ws = w_s2mv + o * 32;
#pragma unroll
        for (int s = 0; s < 32; ++s) a0 += xs[s] * ws[s];
        y[0] += a0;
        const int head = o & 7, hid = o >> 3;
        float* op = out + ((size_t)(b * 8 + head) * ntok + n) * D_ + hid * 16;
#pragma unroll
        for (int x = 0; x < 16; ++x) op[x] = applyMetric ? y[x] * METRICA[x] : y[x];
    }
#pragma unroll
    for (int rr = 0; rr < 2; ++rr) {
        const int o = tid * 2 + rr;
        float y = b_s[o];
        const float* wm = w_mvs2s + o * 16;
#pragma unroll
        for (int i = 0; i < 16; ++i) y += xmv[i * 16] * wm[i];
        const float* ws = w_s2s + o * 32;
#pragma unroll
        for (int s = 0; s < 32; ++s) y += xs[s] * ws[s];
        const int head = o & 7, hid = o >> 3;
        out[((size_t)(b * 8 + head) * ntok + n) * D_ + 256 + hid] = y;
    }
}

// ============================================================================
// Repack kernels (unchanged from R5).
// ============================================================================
#define STG_STRIDE 292
__global__ void repackQ_kernel()
{
    extern __shared__ float ss[];
    const int qt = blockIdx.x, bh = blockIdx.y, tid = threadIdx.x;
    const float SCALE = 0.0589255650988789f;
    const float* src = QB + ((size_t)bh * NQ_ + qt * 64) * D_;
#pragma unroll
    for (int i = 0; i < 18; ++i) {
        int idx = i * 256 + tid, row = idx / 72, c4 = idx % 72;
        float4 v = *(const float4*)(src + (size_t)row * D_ + c4 * 4);
        float* d = ss + row * STG_STRIDE + c4 * 4;
        d[0] = v.x; d[1] = v.y; d[2] = v.z; d[3] = v.w;
    }
    __syncthreads();
    float* dst = QF + (size_t)(bh * 16 + qt) * 18432;
#pragma unroll
    for (int i = 0; i < 18; ++i) {
        int e = i * 256 + tid;
        int m = e / 1152, rem = e % 1152, ds = rem >> 5, lane = rem & 31;
        int g = lane >> 2, t = lane & 3;
        int r0 = m * 16 + g, c0 = ds * 8 + t;
        float4 v;
        v.x = tf32f(ss[r0 * STG_STRIDE + c0] * SCALE);
        v.y = tf32f(ss[(r0 + 8) * STG_STRIDE + c0] * SCALE);
        v.z = tf32f(ss[r0 * STG_STRIDE + c0 + 4] * SCALE);
        v.w = tf32f(ss[(r0 + 8) * STG_STRIDE + c0 + 4] * SCALE);
        *(float4*)(dst + (size_t)e * 4) = v;
    }
}

__global__ void repackK_kernel()
{
    extern __shared__ float ss[];
    const int kt = blockIdx.x, bh = blockIdx.y, tid = threadIdx.x;
    const float* src = KB + ((size_t)bh * NKV_ + kt * 64) * D_;
#pragma unroll
    for (int i = 0; i < 18; ++i) {
        int idx = i * 256 + tid, row = idx / 72, c4 = idx % 72;
        float4 v = *(const float4*)(src + (size_t)row * D_ + c4 * 4);
        float* d = ss + row * STG_STRIDE + c4 * 4;
        d[0] = v.x; d[1] = v.y; d[2] = v.z; d[3] = v.w;
    }
    __syncthreads();
    float* dst = KF + (size_t)(bh * 32 + kt) * 18432;
#pragma unroll
    for (int i = 0; i < 36; ++i) {
        int e = i * 256 + tid;
        int lane = e & 31, tmp = e >> 5;
        int dsl = tmp % 12; tmp /= 12;
        int n = tmp & 7, chunk = tmp >> 3;
        int g = lane >> 2, t = lane & 3;
        int row = n * 8 + g, col = (chunk * 12 + dsl) * 8 + t;
        float2 v = { tf32f(ss[row * STG_STRIDE + col]),
                     tf32f(ss[row * STG_STRIDE + col + 4]) };
        *(float2*)(dst + (size_t)e * 2) = v;
    }
}

__global__ void repackV_kernel()
{
    extern __shared__ float ss[];
    const int kt = blockIdx.x, bh = blockIdx.y, tid = threadIdx.x;
    const float* src = VB + ((size_t)bh * NKV_ + kt * 64) * D_;
#pragma unroll
    for (int i = 0; i < 18; ++i) {
        int idx = i * 256 + tid, row = idx / 72, c4 = idx % 72;
        float4 v = *(const float4*)(src + (size_t)row * D_ + c4 * 4);
        float* d = ss + row * STG_STRIDE + c4 * 4;
        d[0] = v.x; d[1] = v.y; d[2] = v.z; d[3] = v.w;
    }
    __syncthreads();
    float* dst = VF + (size_t)(bh * 32 + kt) * 18432;
#pragma unroll
    for (int i = 0; i < 36; ++i) {
        int e = i * 256 + tid;
        int lane = e & 31, tmp = e >> 5;
        int ntl = tmp % 12; tmp /= 12;
        int ks = tmp & 7, chunk = tmp >> 3;
        int g = lane >> 2, t = lane & 3;
        int col = chunk * 96 + ntl * 8 + g, row0 = ks * 8 + t;
        float2 v = { tf32f(ss[row0 * STG_STRIDE + col]),
                     tf32f(ss[(row0 + 4) * STG_STRIDE + col]) };
        *(float2*)(dst + (size_t)e * 2) = v;
    }
}

// ============================================================================
// Flash attention: 512 threads, 3-buffer ring fed by cp.async.bulk.
// grid=(16,32).
// ============================================================================
#define QS_OFF   0
#define BUF_OFF  18432
#define CHUNK_F  6144
#define CHUNK_B  24576
#define PS_OFF   36864
#define RED_OFF  41216
#define MR_OFF   41728
#define LR_OFF   41792
#define AR_OFF   41856
#define SMF      41920
#define SM_BYTES (SMF * 4 + 64)
#define PSTR 68

__device__ __forceinline__ void scores_chunk(const float* Qs, const float* buf,
                                             float cS[2][4], int c, int wqS, int wkS, int lane)
{
#pragma unroll
    for (int dsl = 0; dsl < 12; ++dsl) {
        float4 A = *(const float4*)(Qs + ((wqS * 36 + c * 12 + dsl) * 32 + lane) * 4);
        float2 B0 = *(const float2*)(buf + (((2 * wkS) * 12 + dsl) * 32 + lane) * 2);
        float2 B1 = *(const float2*)(buf + (((2 * wkS + 1) * 12 + dsl) * 32 + lane) * 2);
        uint32_t a0 = __float_as_uint(A.x), a1 = __float_as_uint(A.y),
                 a2 = __float_as_uint(A.z), a3 = __float_as_uint(A.w);
        MMA(cS[0], a0, a1, a2, a3, __float_as_uint(B0.x), __float_as_uint(B0.y));
        MMA(cS[1], a0, a1, a2, a3, __float_as_uint(B1.x), __float_as_uint(B1.y));
    }
}

__device__ __forceinline__ void pv_chunk(const float* Ps, const float* buf,
                                         float O[3][4], int wqP, int wdP, int g, int t, int lane)
{
#pragma unroll
    for (int ks = 0; ks < 8; ++ks) {
        const float* pb = Ps + (wqP * 16 + g) * PSTR + ks * 8 + t;
        uint32_t a0 = __float_as_uint(pb[0]);
        uint32_t a1 = __float_as_uint(pb[8 * PSTR]);
        uint32_t a2 = __float_as_uint(pb[4]);
        uint32_t a3 = __float_as_uint(pb[8 * PSTR + 4]);
#pragma unroll
        for (int j = 0; j < 3; ++j) {
            float2 Bv = *(const float2*)(buf + ((ks * 12 + wdP * 3 + j) * 32 + lane) * 2);
            MMA(O[j], a0, a1, a2, a3, __float_as_uint(Bv.x), __float_as_uint(Bv.y));
        }
    }
}

__global__ __launch_bounds__(512, 1) void attn6_kernel()
{
    extern __shared__ float sm[];
    float* Qs   = sm + QS_OFF;
    float* buf0 = sm + BUF_OFF;
    float* buf1 = buf0 + CHUNK_F;
    float* buf2 = buf1 + CHUNK_F;
    float* Ps   = sm + PS_OFF;
    float* red  = sm + RED_OFF;
    float* mrow = sm + MR_OFF;
    float* lrow = sm + LR_OFF;
    float* arow = sm + AR_OFF;

    const int tid = threadIdx.x, bh = blockIdx.y, qt = blockIdx.x;
    const int w = tid >> 5, lane = tid & 31, g = lane >> 2, t = lane & 3;
    const int wqS = w & 3, wkS = w >> 2;     // scores: 16q x 16k per warp
    const int wqP = w & 3, wdP = w >> 2;     // PV: 16q x 24d per warp
    const int r = tid >> 3, seg = tid & 7;   // softmax: 8 threads / row

    const uint32_t sb = smem_u32(sm);
    const uint32_t mbase = sb + SMF * 4;
    const uint32_t mbQ = mbase + 24;
    float* bufs[3] = { buf0, buf1, buf2 };

    const float* KFb = KF + (size_t)(bh * 32) * 18432;
    const float* VFb = VF + (size_t)(bh * 32) * 18432;

    if (tid == 0) {
        MB_INIT(mbase + 0, 1); MB_INIT(mbase + 8, 1); MB_INIT(mbase + 16, 1);
        MB_INIT(mbQ, 1);
    }
    __syncthreads();
    if (tid == 0) {
        MB_EXPECT(mbQ, 73728u);
        bulkld(sb + QS_OFF * 4, QF + (size_t)(bh * 16 + qt) * 18432, mbQ, 73728u);
#pragma unroll
        for (int c = 0; c < 3; ++c) {
            MB_EXPECT(mbase + 8 * c, CHUNK_B);
            bulkld(sb + BUF_OFF * 4 + c * CHUNK_B, KFb + c * CHUNK_F, mbase + 8 * c, CHUNK_B);
        }
    }
    if (tid < 64) { mrow[tid] = -1e30f; lrow[tid] = 0.f; }
    MB_WAIT(mbQ, 0);

    float O[3][3][4];
#pragma unroll
    for (int c = 0; c < 3; ++c)
#pragma unroll
        for (int j = 0; j < 3; ++j)
#pragma unroll
            for (int k = 0; k < 4; ++k) O[c][j][k] = 0.f;

    for (int kt = 0; kt < 32; ++kt) {
        const float* VFt = VFb + (size_t)kt * 18432;
        const float* KFn = VFb != 0 ? KFb + (size_t)(kt + 1) * 18432 : 0;

        float cS[2][4];
#pragma unroll
        for (int nt = 0; nt < 2; ++nt)
#pragma unroll
            for (int k = 0; k < 4; ++k) cS[nt][k] = 0.f;

        // ---- scores over 3 chunks; V load chases each consumed chunk ----
#pragma unroll
        for (int c = 0; c < 3; ++c) {
            MB_WAIT(mbase + 8 * c, 0);                     // K chunk c (parity 0)
            scores_chunk(Qs, bufs[c], cS, c, wqS, wkS, lane);
            __syncthreads();                               // all warps done with buf c
            if (tid == 0) {
                MB_EXPECT(mbase + 8 * c, CHUNK_B);
                bulkld(sb + BUF_OFF * 4 + c * CHUNK_B, VFt + c * CHUNK_F, mbase + 8 * c, CHUNK_B);
            }
        }

        // ---- write raw scores ----
#pragma unroll
        for (int nt = 0; nt < 2; ++nt) {
            int row = wqS * 16 + g, col = wkS * 16 + nt * 8 + 2 * t;
            *(float2*)(Ps + row * PSTR + col) = make_float2(cS[nt][0], cS[nt][1]);
            *(float2*)(Ps + (row + 8) * PSTR + col) = make_float2(cS[nt][2], cS[nt][3]);
        }
        __syncthreads();

        // ---- softmax ----
        {
            float lm = -1e30f;
            const float* pr = Ps + r * PSTR + seg * 8;
#pragma unroll
            for (int j = 0; j < 8; ++j) lm = fmaxf(lm, pr[j]);
            red[tid] = lm;
        }
        __syncthreads();
        if (tid < 64) {
            float m8 = red[8 * tid];
#pragma unroll
            for (int j = 1; j < 8; ++j) m8 = fmaxf(m8, red[8 * tid + j]);
            float mo = mrow[tid], mn = fmaxf(mo, m8);
            mrow[tid] = mn; arow[tid] = __expf(mo - mn);
        }
        __syncthreads();
        {
            float mn = mrow[r], s = 0.f;
            float* pw = Ps + r * PSTR + seg * 8;
#pragma unroll
            for (int j = 0; j < 8; ++j) {
                float p = __expf(pw[j] - mn);
                pw[j] = tf32f(p); s += p;
            }
            red[tid] = s;
        }
        {
            float al0 = arow[wqP * 16 + g], al1 = arow[wqP * 16 + 8 + g];
#pragma unroll
            for (int c = 0; c < 3; ++c)
#pragma unroll
                for (int j = 0; j < 3; ++j) {
                    O[c][j][0] *= al0; O[c][j][1] *= al0;
                    O[c][j][2] *= al1; O[c][j][3] *= al1;
                }
        }
        __syncthreads();
        if (tid < 64) {
            float s8 = 0.f;
#pragma unroll
            for (int j = 0; j < 8; ++j) s8 += red[8 * tid + j];
            lrow[tid] = lrow[tid] * arow[tid] + s8;
        }

        // ---- PV over 3 chunks; next-K load chases each consumed chunk ----
#pragma unroll
        for (int c = 0; c < 3; ++c) {
            MB_WAIT(mbase + 8 * c, 1);                     // V chunk c (parity 1)
            pv_chunk(Ps, bufs[c], O[c], wqP, wdP, g, t, lane);
            __syncthreads();
            if (kt < 31 && tid == 0) {
                MB_EXPECT(mbase + 8 * c, CHUNK_B);
                bulkld(sb + BUF_OFF * 4 + c * CHUNK_B, KFn + c * CHUNK_F, mbase + 8 * c, CHUNK_B);
            }
        }
    }

    __syncthreads();
    const float li0 = 1.f / lrow[wqP * 16 + g];
    const float li1 = 1.f / lrow[wqP * 16 + 8 + g];
    const int b = bh >> 3, hh = bh & 7;
    const int q0 = qt * 64 + wqP * 16 + g;
#pragma unroll
    for (int c = 0; c < 3; ++c)
#pragma unroll
        for (int j = 0; j < 3; ++j) {
            int d = c * 96 + (wdP * 3 + j) * 8 + 2 * t;
            size_t o0 = (((size_t)(b * NQ_ + q0)) * 8 + hh) * D_ + d;
            size_t o1 = (((size_t)(b * NQ_ + q0 + 8)) * 8 + hh) * D_ + d;
            *(float2*)(OB + o0) = make_float2(O[c][j][0] * li0, O[c][j][1] * li0);
            *(float2*)(OB + o1) = make_float2(O[c][j][2] * li1, O[c][j][3] * li1);
        }
}

// ============================================================================
// Output projection (unchanged).
// ============================================================================
__global__ void outproj_kernel(const float* __restrict__ wo_mv, const float* __restrict__ wo_s2mv,
                               const float* __restrict__ wo_mvs2s, const float* __restrict__ wo_s2s,
                               const float* __restrict__ bo_mv, const float* __restrict__ bo_s,
                               float* __restrict__ d_out)
{
    __shared__ float xm[2048];
    __shared__ float xsc[256];
    const int t = blockIdx.x, tid = threadIdx.x;
    const float* ob = OB + (size_t)t * 8 * D_;
    for (int idx = tid; idx < 2048; idx += 256) {
        const int c = idx >> 4, x = idx & 15, head = c >> 4, hid = c & 15;
        xm[idx] = ob[head * D_ + hid * 16 + x];
    }
    {
        const int head = tid >> 5, hid = tid & 31;
        xsc[tid] = ob[head * D_ + 256 + hid];
    }
    __syncthreads();
    {
        const int o = tid >> 4, x = tid & 15, gg = GRADE_RT[x];
        const float* wmx = wo_mv + (size_t)o * 128 * 5 + gg;
        float y = 0.f;
#pragma unroll 8
        for (int i = 0; i < 128; ++i) y += xm[i * 16 + x] * wmx[i * 5];
        if (x == 0) {
            float a = bo_mv[o];
            const float* ws = wo_s2mv + o * 256;
#pragma unroll 8
            for (int s = 0; s < 256; ++s) a += xsc[s] * ws[s];
            y += a;
        }
        d_out[(size_t)t * 256 + o * 16 + x] = y;
    }
    if (tid < 32) {
        const int o = tid;
        float y = bo_s[o];
        const float* wm = wo_mvs2s + o * 128;
#pragma unroll 8
        for (int i = 0; i < 128; ++i) y += xm[i * 16] * wm[i];
        const float* ws = wo_s2s + o * 256;
#pragma unroll 8
        for (int s = 0; s < 256; ++s) y += xsc[s] * ws[s];
        d_out[(size_t)B_ * NQ_ * 256 + (size_t)t * 32 + o] = y;
    }
}

extern "C" void kernel_launch(void* const* d_in, const int* in_sizes, int n_in,
                              void* d_out, int out_size)
{
    (void)in_sizes; (void)n_in; (void)out_size;
    const float* mv_kv = (const float*)d_in[0];
    const float* mv_q  = (const float*)d_in[1];
    const float* s_kv  = (const float*)d_in[2];
    const float* s_q   = (const float*)d_in[3];
    const float* wq_mv = (const float*)d_in[4],  *wq_s2mv = (const float*)d_in[5];
    const float* wq_m2s = (const float*)d_in[6], *wq_s2s = (const float*)d_in[7];
    const float* bq_mv = (const float*)d_in[8],  *bq_s = (const float*)d_in[9];
    const float* wk_mv = (const float*)d_in[10], *wk_s2mv = (const float*)d_in[11];
    const float* wk_m2s = (const float*)d_in[12],*wk_s2s = (const float*)d_in[13];
    const float* bk_mv = (const float*)d_in[14], *bk_s = (const float*)d_in[15];
    const float* wv_mv = (const float*)d_in[16], *wv_s2mv = (const float*)d_in[17];
    const float* wv_m2s = (const float*)d_in[18],*wv_s2s = (const float*)d_in[19];
    const float* bv_mv = (const float*)d_in[20], *bv_s = (const float*)d_in[21];
    const float* wo_mv = (const float*)d_in[22], *wo_s2mv = (const float*)d_in[23];
    const float* wo_m2s = (const float*)d_in[24],*wo_s2s = (const float*)d_in[25];
    const float* bo_mv = (const float*)d_in[26], *bo_s = (const float*)d_in[27];

    const int stage_smem = 64 * STG_STRIDE * sizeof(float);
    cudaFuncSetAttribute(repackQ_kernel, cudaFuncAttributeMaxDynamicSharedMemorySize, stage_smem);
    cudaFuncSetAttribute(repackK_kernel, cudaFuncAttributeMaxDynamicSharedMemorySize, stage_smem);
    cudaFuncSetAttribute(repackV_kernel, cudaFuncAttributeMaxDynamicSharedMemorySize, stage_smem);
    cudaFuncSetAttribute(attn6_kernel, cudaFuncAttributeMaxDynamicSharedMemorySize, SM_BYTES);

    proj_kernel<<<B_ * NQ_, 128>>>(mv_q, s_q, wq_mv, wq_s2mv, wq_m2s, wq_s2s, bq_mv, bq_s, NQ_, 0, 0);
    proj_kernel<<<B_ * NKV_, 128>>>(mv_kv, s_kv, wk_mv, wk_s2mv, wk_m2s, wk_s2s, bk_mv, bk_s, NKV_, 1, 1);
    proj_kernel<<<B_ * NKV_, 128>>>(mv_kv, s_kv, wv_mv, wv_s2mv, wv_m2s, wv_s2s, bv_mv, bv_s, NKV_, 2, 0);

    repackQ_kernel<<<dim3(16, 32), 256, stage_smem>>>();
    repackK_kernel<<<dim3(32, 32), 256, stage_smem>>>();
    repackV_kernel<<<dim3(32, 32), 256, stage_smem>>>();

    attn6_kernel<<<dim3(16, 32), 512, SM_BYTES>>>();

    outproj_kernel<<<B_ * NQ_, 256>>>(wo_mv, wo_s2mv, wo_m2s, wo_s2s, bo_mv, bo_s, (float*)d_out);
}

// round 8
// speedup vs baseline: 1.0824x; 1.0116x over previous
#include <cuda_runtime.h>
#include <cuda_bf16.h>
#include <math.h>
#include <stdint.h>

#define B_    4
#define NQ_   1024
#define NKV_  2048
#define D_    288

__device__ constexpr int   GRADEA[16] = {0,1,1,1,1,2,2,2,2,2,2,3,3,3,3,4};
__device__ constexpr float METRICA[16] = {1.f,1.f,-1.f,-1.f,-1.f,-1.f,-1.f,-1.f,
                                          1.f,1.f, 1.f, 1.f, 1.f, 1.f,-1.f,-1.f};
__constant__ int GRADE_RT[16] = {0,1,1,1,1,2,2,2,2,2,2,3,3,3,3,4};

// scratch
__device__ __align__(1024) float QB[(size_t)B_*8*NQ_*D_];
__device__ __align__(1024) float KB[(size_t)B_*8*NKV_*D_];
__device__ __align__(1024) float VB[(size_t)B_*8*NKV_*D_];
__device__ __align__(1024) float OB[(size_t)B_*NQ_*8*D_];
// packed bf16x2 fragment images
// QF: [bh][qt16][ hi:9216 | lo:9216 ] u32   (A-frags m16n8k16, [m4][ks18][lane32][4])
// KF: [bh][kt32][chunk3][ hl2 ][n8][ksl6][lane32][2] u32  (24576B per chunk)
// VF: [bh][kt32][chunk3][ntl12][ks4][lane32][2] u32       (12288B per chunk)
__device__ __align__(1024) uint32_t QFG[(size_t)32*16*18432];
__device__ __align__(1024) uint32_t KFG[(size_t)32*32*3*6144];
__device__ __align__(1024) uint32_t VFG[(size_t)32*32*3*3072];

__device__ __forceinline__ uint32_t pk2b(float lo, float hi) {
    __nv_bfloat162 h = __floats2bfloat162_rn(lo, hi);
    return *(uint32_t*)&h;
}
__device__ __forceinline__ float bf16res(float x) {          // residual after bf16 round
    return x - __bfloat162float(__float2bfloat16_rn(x));
}
#define MMA16(c,a0,a1,a2,a3,b0,b1) \
    asm volatile("mma.sync.aligned.m16n8k16.row.col.f32.bf16.bf16.f32 " \
        "{%0,%1,%2,%3},{%4,%5,%6,%7},{%8,%9},{%0,%1,%2,%3};" \
        : "+f"((c)[0]),"+f"((c)[1]),"+f"((c)[2]),"+f"((c)[3]) \
        : "r"(a0),"r"(a1),"r"(a2),"r"(a3),"r"(b0),"r"(b1))

__device__ __forceinline__ uint32_t smem_u32(const void* p) {
    uint32_t a;
    asm("{ .reg .u64 t; cvta.to.shared.u64 t, %1; cvt.u32.u64 %0, t; }" : "=r"(a) : "l"(p));
    return a;
}
__device__ __forceinline__ void bulkld(uint32_t sdst, const void* gsrc, uint32_t mbar, uint32_t bytes) {
    asm volatile("cp.async.bulk.shared::cluster.global.mbarrier::complete_tx::bytes [%0], [%1], %2, [%3];"
        :: "r"(sdst), "l"(gsrc), "r"(bytes), "r"(mbar) : "memory");
}
#define MB_INIT(mb, c)    asm volatile("mbarrier.init.shared.b64 [%0], %1;" :: "r"(mb), "r"(c) : "memory")
#define MB_EXPECT(mb, nb) asm volatile("mbarrier.arrive.expect_tx.shared.b64 _, [%0], %1;" :: "r"(mb), "r"(nb) : "memory")
#define MB_WAIT(mb, par) do { \
    asm volatile("{\n\t.reg .pred P1;\n\tWL_%=:\n\t" \
        "mbarrier.try_wait.parity.acquire.cta.shared::cta.b64 P1, [%0], %1, 0x989680;\n\t" \
        "@P1 bra.uni WD_%=;\n\tbra.uni WL_%=;\n\tWD_%=:\n\t}" \
        :: "r"(mb), "r"(par) : "memory"); } while (0)

// ============================================================================
// QKV projection (unchanged).
// ============================================================================
__global__ void proj_kernel(const float* __restrict__ x_mv, const float* __restrict__ x_s,
                            const float* __restrict__ w_mv, const float* __restrict__ w_s2mv,
                            const float* __restrict__ w_mvs2s, const float* __restrict__ w_s2s,
                            const float* __restrict__ b_mv, const float* __restrict__ b_s,
                            int ntok, int dst, int applyMetric)
{
    __shared__ float xmv[256];
    __shared__ float xs[32];
    const int t = blockIdx.x, b = t / ntok, n = t % ntok, tid = threadIdx.x;
    const float* xp = x_mv + (size_t)t * 256;
    xmv[tid] = xp[tid]; xmv[tid + 128] = xp[tid + 128];
    if (tid < 32) xs[tid] = x_s[(size_t)t * 32 + tid];
    __syncthreads();
    float* out = (dst == 0) ? QB : (dst == 1) ? KB : VB;
    {
        const int o = tid;
        const float* wr = w_mv + o * 80;
        float y[16];
#pragma unroll
        for (int x = 0; x < 16; ++x) {
            float acc = 0.f;
#pragma unroll
            for (int i = 0; i < 16; ++i) acc += xmv[i * 16 + x] * wr[i * 5 + GRADEA[x]];
            y[x] = acc;
        }
        float a0 = b_mv[o];
        const float* ws = w_s2mv + o * 32;
#pragma unroll
        for (int s = 0; s < 32; ++s) a0 += xs[s] * ws[s];
        y[0] += a0;
        const int head = o & 7, hid = o >> 3;
        float* op = out + ((size_t)(b * 8 + head) * ntok + n) * D_ + hid * 16;
#pragma unroll
        for (int x = 0; x < 16; ++x) op[x] = applyMetric ? y[x] * METRICA[x] : y[x];
    }
#pragma unroll
    for (int rr = 0; rr < 2; ++rr) {
        const int o = tid * 2 + rr;
        float y = b_s[o];
        const float* wm = w_mvs2s + o * 16;
#pragma unroll
        for (int i = 0; i < 16; ++i) y += xmv[i * 16] * wm[i];
        const float* ws = w_s2s + o * 32;
#pragma unroll
        for (int s = 0; s < 32; ++s) y += xs[s] * ws[s];
        const int head = o & 7, hid = o >> 3;
        out[((size_t)(b * 8 + head) * ntok + n) * D_ + 256 + hid] = y;
    }
}

// ============================================================================
// Repack kernels: stage 64x288 fp32 tile, emit packed bf16x2 hi/lo fragments.
// ============================================================================
#define STG_STRIDE 292
__device__ __forceinline__ void stage_tile(float* ss, const float* src, int tid)
{
#pragma unroll
    for (int i = 0; i < 18; ++i) {
        int idx = i * 256 + tid, row = idx / 72, c4 = idx % 72;
        float4 v = *(const float4*)(src + (size_t)row * D_ + c4 * 4);
        float* d = ss + row * STG_STRIDE + c4 * 4;
        d[0] = v.x; d[1] = v.y; d[2] = v.z; d[3] = v.w;
    }
}

__global__ void repackQ_kernel()   // grid(16,32)
{
    extern __shared__ float ss[];
    const int qt = blockIdx.x, bh = blockIdx.y, tid = threadIdx.x;
    const float SCALE = 0.0589255650988789f;   // 1/sqrt(288), folded into Q
    stage_tile(ss, QB + ((size_t)bh * NQ_ + qt * 64) * D_, tid);
    __syncthreads();
    uint32_t* dst = QFG + (size_t)(bh * 16 + qt) * 18432;
    // groups: (m4, ks18, lane32) -> 4 u32 hi + 4 u32 lo
#pragma unroll
    for (int i = 0; i < 9; ++i) {
        int e = i * 256 + tid;                 // 0..2303
        int m = e / 576, rem = e % 576, ks = rem >> 5, lane = rem & 31;
        int g = lane >> 2, t = lane & 3;
        int r0 = m * 16 + g, c0 = ks * 16 + 2 * t;
        float v[8];
        v[0] = ss[r0 * STG_STRIDE + c0] * SCALE;       v[1] = ss[r0 * STG_STRIDE + c0 + 1] * SCALE;
        v[2] = ss[(r0+8) * STG_STRIDE + c0] * SCALE;   v[3] = ss[(r0+8) * STG_STRIDE + c0 + 1] * SCALE;
        v[4] = ss[r0 * STG_STRIDE + c0 + 8] * SCALE;   v[5] = ss[r0 * STG_STRIDE + c0 + 9] * SCALE;
        v[6] = ss[(r0+8) * STG_STRIDE + c0 + 8] * SCALE; v[7] = ss[(r0+8) * STG_STRIDE + c0 + 9] * SCALE;
        uint4 hi = { pk2b(v[0],v[1]), pk2b(v[2],v[3]), pk2b(v[4],v[5]), pk2b(v[6],v[7]) };
        uint4 lo = { pk2b(bf16res(v[0]),bf16res(v[1])), pk2b(bf16res(v[2]),bf16res(v[3])),
                     pk2b(bf16res(v[4]),bf16res(v[5])), pk2b(bf16res(v[6]),bf16res(v[7])) };
        *(uint4*)(dst + (size_t)e * 4)          = hi;
        *(uint4*)(dst + 9216 + (size_t)e * 4)   = lo;
    }
}

__global__ void repackK_kernel()   // grid(32,32)
{
    extern __shared__ float ss[];
    const int kt = blockIdx.x, bh = blockIdx.y, tid = threadIdx.x;
    stage_tile(ss, KB + ((size_t)bh * NKV_ + kt * 64) * D_, tid);
    __syncthreads();
    uint32_t* dst = KFG + (size_t)(bh * 32 + kt) * 3 * 6144;
    // groups: (c3, n8, ksl6, lane32) -> write hi pair + lo pair
#pragma unroll
    for (int i = 0; i < 18; ++i) {
        int e = i * 256 + tid;                 // 0..4607
        int c = e / 1536, rem = e % 1536;
        int n = rem / 192, rem2 = rem % 192, ksl = rem2 >> 5, lane = rem2 & 31;
        int g = lane >> 2, t = lane & 3;
        int key = n * 8 + g, d0 = c * 96 + ksl * 16 + 2 * t;
        float x0 = ss[key * STG_STRIDE + d0],     x1 = ss[key * STG_STRIDE + d0 + 1];
        float x2 = ss[key * STG_STRIDE + d0 + 8], x3 = ss[key * STG_STRIDE + d0 + 9];
        uint32_t* ch = dst + (size_t)c * 6144;
        int go = ((n * 6 + ksl) * 32 + lane) * 2;
        uint2 hi = { pk2b(x0, x1), pk2b(x2, x3) };
        uint2 lo = { pk2b(bf16res(x0), bf16res(x1)), pk2b(bf16res(x2), bf16res(x3)) };
        *(uint2*)(ch + go)        = hi;
        *(uint2*)(ch + 3072 + go) = lo;
    }
}

__global__ void repackV_kernel()   // grid(32,32)
{
    extern __shared__ float ss[];
    const int kt = blockIdx.x, bh = blockIdx.y, tid = threadIdx.x;
    stage_tile(ss, VB + ((size_t)bh * NKV_ + kt * 64) * D_, tid);
    __syncthreads();
    uint32_t* dst = VFG + (size_t)(bh * 32 + kt) * 3 * 3072;
    // groups: (c3, ntl12, ks4, lane32) -> 2 u32 (plain bf16)
#pragma unroll
    for (int i = 0; i < 18; ++i) {
        int e = i * 256 + tid;                 // 0..4607
        int c = e / 1536, rem = e % 1536;
        int ntl = rem / 128, rem2 = rem % 128, ks = rem2 >> 5, lane = rem2 & 31;
        int g = lane >> 2, t = lane & 3;
        int key0 = ks * 16 + 2 * t, d = c * 96 + ntl * 8 + g;
        uint2 v = { pk2b(ss[key0 * STG_STRIDE + d],       ss[(key0+1) * STG_STRIDE + d]),
                    pk2b(ss[(key0+8) * STG_STRIDE + d],   ss[(key0+9) * STG_STRIDE + d]) };
        *(uint2*)(dst + (size_t)c * 3072 + ((ntl * 4 + ks) * 32 + lane) * 2) = v;
    }
}

// ============================================================================
// Flash attention: 512 threads, split-bf16 native MMA, bulk 3-buffer ring.
// grid=(16,32).
// ============================================================================
#define QFH_OFF  0
#define QFL_OFF  9216
#define BUF_OFF  18432
#define BUFW     6144
#define SS_OFF   36864
#define PSH_OFF  41216
#define PSL_OFF  43520
#define RED_OFF  45824
#define MR_OFF   46336
#define LR_OFF   46400
#define AR_OFF   46464
#define SMF      46528
#define SM_BYTES (SMF * 4 + 64)
#define PSTR 68
#define PPS  36   // packed P row stride in u32

__device__ __forceinline__ void scores_chunk(const uint32_t* Qh, const uint32_t* Ql,
                                             const uint32_t* buf, float cS[2][4],
                                             int c, int wqS, int wkS, int lane)
{
#pragma unroll
    for (int ksl = 0; ksl < 6; ++ksl) {
        int ksg = c * 6 + ksl;
        uint4 Ah = *(const uint4*)(Qh + ((wqS * 18 + ksg) * 32 + lane) * 4);
        uint4 Al = *(const uint4*)(Ql + ((wqS * 18 + ksg) * 32 + lane) * 4);
        uint2 kh0 = *(const uint2*)(buf + (((0 + 2*wkS)     * 6 + ksl) * 32 + lane) * 2);
        uint2 kh1 = *(const uint2*)(buf + (((0 + 2*wkS + 1) * 6 + ksl) * 32 + lane) * 2);
        uint2 kl0 = *(const uint2*)(buf + 3072 + (((2*wkS)     * 6 + ksl) * 32 + lane) * 2);
        uint2 kl1 = *(const uint2*)(buf + 3072 + (((2*wkS + 1) * 6 + ksl) * 32 + lane) * 2);
        MMA16(cS[0], Ah.x, Ah.y, Ah.z, Ah.w, kh0.x, kh0.y);
        MMA16(cS[1], Ah.x, Ah.y, Ah.z, Ah.w, kh1.x, kh1.y);
        MMA16(cS[0], Ah.x, Ah.y, Ah.z, Ah.w, kl0.x, kl0.y);
        MMA16(cS[1], Ah.x, Ah.y, Ah.z, Ah.w, kl1.x, kl1.y);
        MMA16(cS[0], Al.x, Al.y, Al.z, Al.w, kh0.x, kh0.y);
        MMA16(cS[1], Al.x, Al.y, Al.z, Al.w, kh1.x, kh1.y);
    }
}

__device__ __forceinline__ void pv_chunk(const uint32_t* Psh, const uint32_t* Psl,
                                         const uint32_t* buf, float O[3][4],
                                         int wqP, int wdP, int g, int t, int lane)
{
#pragma unroll
    for (int ks = 0; ks < 4; ++ks) {
        const int r0 = wqP * 16, ci = ks * 8 + t;
        uint32_t ah0 = Psh[(r0 + g) * PPS + ci];
        uint32_t ah1 = Psh[(r0 + 8 + g) * PPS + ci];
        uint32_t ah2 = Psh[(r0 + g) * PPS + ci + 4];
        uint32_t ah3 = Psh[(r0 + 8 + g) * PPS + ci + 4];
        uint32_t al0 = Psl[(r0 + g) * PPS + ci];
        uint32_t al1 = Psl[(r0 + 8 + g) * PPS + ci];
        uint32_t al2 = Psl[(r0 + g) * PPS + ci + 4];
        uint32_t al3 = Psl[(r0 + 8 + g) * PPS + ci + 4];
#pragma unroll
        for (int j = 0; j < 3; ++j) {
            int ntl = wdP * 3 + j;
            uint2 Bv = *(const uint2*)(buf + ((ntl * 4 + ks) * 32 + lane) * 2);
            MMA16(O[j], ah0, ah1, ah2, ah3, Bv.x, Bv.y);
            MMA16(O[j], al0, al1, al2, al3, Bv.x, Bv.y);
        }
    }
}

__global__ __launch_bounds__(512, 1) void attn7_kernel()
{
    extern __shared__ float sm[];
    uint32_t* Qh  = (uint32_t*)sm + QFH_OFF;
    uint32_t* Ql  = (uint32_t*)sm + QFL_OFF;
    uint32_t* bufs[3] = { (uint32_t*)sm + BUF_OFF, (uint32_t*)sm + BUF_OFF + BUFW,
                          (uint32_t*)sm + BUF_OFF + 2 * BUFW };
    float*    Ss  = sm + SS_OFF;
    uint32_t* Psh = (uint32_t*)sm + PSH_OFF;
    uint32_t* Psl = (uint32_t*)sm + PSL_OFF;
    float*    red = sm + RED_OFF;
    float*    mrow = sm + MR_OFF;
    float*    lrow = sm + LR_OFF;
    float*    arow = sm + AR_OFF;

    const int tid = threadIdx.x, bh = blockIdx.y, qt = blockIdx.x;
    const int w = tid >> 5, lane = tid & 31, g = lane >> 2, t = lane & 3;
    const int wqS = w & 3, wkS = w >> 2;
    const int wqP = w & 3, wdP = w >> 2;
    const int r = tid >> 3, seg = tid & 7;

    const uint32_t sb = smem_u32(sm);
    const uint32_t mbase = sb + SMF * 4;
    const uint32_t mbQ = mbase + 24;

    const uint32_t* KFb = KFG + (size_t)(bh * 32) * 3 * 6144;
    const uint32_t* VFb = VFG + (size_t)(bh * 32) * 3 * 3072;

    if (tid == 0) {
        MB_INIT(mbase + 0, 1); MB_INIT(mbase + 8, 1); MB_INIT(mbase + 16, 1);
        MB_INIT(mbQ, 1);
    }
    __syncthreads();
    if (tid == 0) {
        MB_EXPECT(mbQ, 73728u);
        bulkld(sb + QFH_OFF * 4, QFG + (size_t)(bh * 16 + qt) * 18432, mbQ, 73728u);
#pragma unroll
        for (int c = 0; c < 3; ++c) {
            MB_EXPECT(mbase + 8 * c, 24576u);
            bulkld(sb + (BUF_OFF + c * BUFW) * 4, KFb + c * 6144, mbase + 8 * c, 24576u);
        }
    }
    if (tid < 64) { mrow[tid] = -1e30f; lrow[tid] = 0.f; }
    MB_WAIT(mbQ, 0);

    float O[3][3][4];
#pragma unroll
    for (int c = 0; c < 3; ++c)
#pragma unroll
        for (int j = 0; j < 3; ++j)
#pragma unroll
            for (int k = 0; k < 4; ++k) O[c][j][k] = 0.f;

    for (int kt = 0; kt < 32; ++kt) {
        const uint32_t* VFt = VFb + (size_t)kt * 3 * 3072;
        const uint32_t* KFn = KFb + (size_t)(kt + 1) * 3 * 6144;

        float cS[2][4];
#pragma unroll
        for (int nt = 0; nt < 2; ++nt)
#pragma unroll
            for (int k = 0; k < 4; ++k) cS[nt][k] = 0.f;

        // ---- scores over 3 chunks; V load chases each consumed chunk ----
#pragma unroll
        for (int c = 0; c < 3; ++c) {
            MB_WAIT(mbase + 8 * c, 0);
            scores_chunk(Qh, Ql, bufs[c], cS, c, wqS, wkS, lane);
            __syncthreads();
            if (tid == 0) {
                MB_EXPECT(mbase + 8 * c, 12288u);
                bulkld(sb + (BUF_OFF + c * BUFW) * 4, VFt + c * 3072, mbase + 8 * c, 12288u);
            }
        }

        // ---- write raw fp32 scores ----
#pragma unroll
        for (int nt = 0; nt < 2; ++nt) {
            int row = wqS * 16 + g, col = wkS * 16 + nt * 8 + 2 * t;
            *(float2*)(Ss + row * PSTR + col) = make_float2(cS[nt][0], cS[nt][1]);
            *(float2*)(Ss + (row + 8) * PSTR + col) = make_float2(cS[nt][2], cS[nt][3]);
        }
        __syncthreads();

        // ---- softmax (fp32), emit split-bf16 P ----
        {
            float lm = -1e30f;
            const float* pr = Ss + r * PSTR + seg * 8;
#pragma unroll
            for (int j = 0; j < 8; ++j) lm = fmaxf(lm, pr[j]);
            red[tid] = lm;
        }
        __syncthreads();
        if (tid < 64) {
            float m8 = red[8 * tid];
#pragma unroll
            for (int j = 1; j < 8; ++j) m8 = fmaxf(m8, red[8 * tid + j]);
            float mo = mrow[tid], mn = fmaxf(mo, m8);
            mrow[tid] = mn; arow[tid] = __expf(mo - mn);
        }
        __syncthreads();
        {
            float mn = mrow[r], s = 0.f;
            const float* pw = Ss + r * PSTR + seg * 8;
            uint32_t* ph = Psh + r * PPS + seg * 4;
            uint32_t* pl = Psl + r * PPS + seg * 4;
#pragma unroll
            for (int j = 0; j < 4; ++j) {
                float p0 = __expf(pw[2*j] - mn), p1 = __expf(pw[2*j+1] - mn);
                s += p0 + p1;
                ph[j] = pk2b(p0, p1);
                pl[j] = pk2b(bf16res(p0), bf16res(p1));
            }
            red[tid] = s;
        }
        {
            float al0 = arow[wqP * 16 + g], al1 = arow[wqP * 16 + 8 + g];
#pragma unroll
            for (int c = 0; c < 3; ++c)
#pragma unroll
                for (int j = 0; j < 3; ++j) {
                    O[c][j][0] *= al0; O[c][j][1] *= al0;
                    O[c][j][2] *= al1; O[c][j][3] *= al1;
                }
        }
        __syncthreads();
        if (tid < 64) {
            float s8 = 0.f;
#pragma unroll
            for (int j = 0; j < 8; ++j) s8 += red[8 * tid + j];
            lrow[tid] = lrow[tid] * arow[tid] + s8;
        }

        // ---- PV over 3 chunks; next-K load chases each consumed chunk ----
#pragma unroll
        for (int c = 0; c < 3; ++c) {
            MB_WAIT(mbase + 8 * c, 1);
            pv_chunk(Psh, Psl, bufs[c], O[c], wqP, wdP, g, t, lane);
            __syncthreads();
            if (kt < 31 && tid == 0) {
                MB_EXPECT(mbase + 8 * c, 24576u);
                bulkld(sb + (BUF_OFF + c * BUFW) * 4, KFn + c * 6144, mbase + 8 * c, 24576u);
            }
        }
    }

    __syncthreads();
    const float li0 = 1.f / lrow[wqP * 16 + g];
    const float li1 = 1.f / lrow[wqP * 16 + 8 + g];
    const int b = bh >> 3, hh = bh & 7;
    const int q0 = qt * 64 + wqP * 16 + g;
#pragma unroll
    for (int c = 0; c < 3; ++c)
#pragma unroll
        for (int j = 0; j < 3; ++j) {
            int d = c * 96 + (wdP * 3 + j) * 8 + 2 * t;
            size_t o0 = (((size_t)(b * NQ_ + q0)) * 8 + hh) * D_ + d;
            size_t o1 = (((size_t)(b * NQ_ + q0 + 8)) * 8 + hh) * D_ + d;
            *(float2*)(OB + o0) = make_float2(O[c][j][0] * li0, O[c][j][1] * li0);
            *(float2*)(OB + o1) = make_float2(O[c][j][2] * li1, O[c][j][3] * li1);
        }
}

// ============================================================================
// Output projection (unchanged).
// ============================================================================
__global__ void outproj_kernel(const float* __restrict__ wo_mv, const float* __restrict__ wo_s2mv,
                               const float* __restrict__ wo_mvs2s, const float* __restrict__ wo_s2s,
                               const float* __restrict__ bo_mv, const float* __restrict__ bo_s,
                               float* __restrict__ d_out)
{
    __shared__ float xm[2048];
    __shared__ float xsc[256];
    const int t = blockIdx.x, tid = threadIdx.x;
    const float* ob = OB + (size_t)t * 8 * D_;
    for (int idx = tid; idx < 2048; idx += 256) {
        const int c = idx >> 4, x = idx & 15, head = c >> 4, hid = c & 15;
        xm[idx] = ob[head * D_ + hid * 16 + x];
    }
    {
        const int head = tid >> 5, hid = tid & 31;
        xsc[tid] = ob[head * D_ + 256 + hid];
    }
    __syncthreads();
    {
        const int o = tid >> 4, x = tid & 15, gg = GRADE_RT[x];
        const float* wmx = wo_mv + (size_t)o * 128 * 5 + gg;
        float y = 0.f;
#pragma unroll 8
        for (int i = 0; i < 128; ++i) y += xm[i * 16 + x] * wmx[i * 5];
        if (x == 0) {
            float a = bo_mv[o];
            const float* ws = wo_s2mv + o * 256;
#pragma unroll 8
            for (int s = 0; s < 256; ++s) a += xsc[s] * ws[s];
            y += a;
        }
        d_out[(size_t)t * 256 + o * 16 + x] = y;
    }
    if (tid < 32) {
        const int o = tid;
        float y = bo_s[o];
        const float* wm = wo_mvs2s + o * 128;
#pragma unroll 8
        for (int i = 0; i < 128; ++i) y += xm[i * 16] * wm[i];
        const float* ws = wo_s2s + o * 256;
#pragma unroll 8
        for (int s = 0; s < 256; ++s) y += xsc[s] * ws[s];
        d_out[(size_t)B_ * NQ_ * 256 + (size_t)t * 32 + o] = y;
    }
}

extern "C" void kernel_launch(void* const* d_in, const int* in_sizes, int n_in,
                              void* d_out, int out_size)
{
    (void)in_sizes; (void)n_in; (void)out_size;
    const float* mv_kv = (const float*)d_in[0];
    const float* mv_q  = (const float*)d_in[1];
    const float* s_kv  = (const float*)d_in[2];
    const float* s_q   = (const float*)d_in[3];
    const float* wq_mv = (const float*)d_in[4],  *wq_s2mv = (const float*)d_in[5];
    const float* wq_m2s = (const float*)d_in[6], *wq_s2s = (const float*)d_in[7];
    const float* bq_mv = (const float*)d_in[8],  *bq_s = (const float*)d_in[9];
    const float* wk_mv = (const float*)d_in[10], *wk_s2mv = (const float*)d_in[11];
    const float* wk_m2s = (const float*)d_in[12],*wk_s2s = (const float*)d_in[13];
    const float* bk_mv = (const float*)d_in[14], *bk_s = (const float*)d_in[15];
    const float* wv_mv = (const float*)d_in[16], *wv_s2mv = (const float*)d_in[17];
    const float* wv_m2s = (const float*)d_in[18],*wv_s2s = (const float*)d_in[19];
    const float* bv_mv = (const float*)d_in[20], *bv_s = (const float*)d_in[21];
    const float* wo_mv = (const float*)d_in[22], *wo_s2mv = (const float*)d_in[23];
    const float* wo_m2s = (const float*)d_in[24],*wo_s2s = (const float*)d_in[25];
    const float* bo_mv = (const float*)d_in[26], *bo_s = (const float*)d_in[27];

    const int stage_smem = 64 * STG_STRIDE * sizeof(float);
    cudaFuncSetAttribute(repackQ_kernel, cudaFuncAttributeMaxDynamicSharedMemorySize, stage_smem);
    cudaFuncSetAttribute(repackK_kernel, cudaFuncAttributeMaxDynamicSharedMemorySize, stage_smem);
    cudaFuncSetAttribute(repackV_kernel, cudaFuncAttributeMaxDynamicSharedMemorySize, stage_smem);
    cudaFuncSetAttribute(attn7_kernel, cudaFuncAttributeMaxDynamicSharedMemorySize, SM_BYTES);

    proj_kernel<<<B_ * NQ_, 128>>>(mv_q, s_q, wq_mv, wq_s2mv, wq_m2s, wq_s2s, bq_mv, bq_s, NQ_, 0, 0);
    proj_kernel<<<B_ * NKV_, 128>>>(mv_kv, s_kv, wk_mv, wk_s2mv, wk_m2s, wk_s2s, bk_mv, bk_s, NKV_, 1, 1);
    proj_kernel<<<B_ * NKV_, 128>>>(mv_kv, s_kv, wv_mv, wv_s2mv, wv_m2s, wv_s2s, bv_mv, bv_s, NKV_, 2, 0);

    repackQ_kernel<<<dim3(16, 32), 256, stage_smem>>>();
    repackK_kernel<<<dim3(32, 32), 256, stage_smem>>>();
    repackV_kernel<<<dim3(32, 32), 256, stage_smem>>>();

    attn7_kernel<<<dim3(16, 32), 512, SM_BYTES>>>();

    outproj_kernel<<<B_ * NQ_, 256>>>(wo_mv, wo_s2mv, wo_m2s, wo_s2s, bo_mv, bo_s, (float*)d_out);
}

// round 9
// speedup vs baseline: 1.1482x; 1.0608x over previous
#include <cuda_runtime.h>
#include <cuda_bf16.h>
#include <math.h>
#include <stdint.h>

#define B_    4
#define NQ_   1024
#define NKV_  2048
#define D_    288

__device__ constexpr int   GRADEA[16] = {0,1,1,1,1,2,2,2,2,2,2,3,3,3,3,4};
__device__ constexpr float METRICA[16] = {1.f,1.f,-1.f,-1.f,-1.f,-1.f,-1.f,-1.f,
                                          1.f,1.f, 1.f, 1.f, 1.f, 1.f,-1.f,-1.f};
__constant__ int GRADE_RT[16] = {0,1,1,1,1,2,2,2,2,2,2,3,3,3,3,4};

// scratch
__device__ __align__(1024) float QB[(size_t)B_*8*NQ_*D_];
__device__ __align__(1024) float KB[(size_t)B_*8*NKV_*D_];
__device__ __align__(1024) float VB[(size_t)B_*8*NKV_*D_];
__device__ __align__(1024) float OB[(size_t)B_*NQ_*8*D_];
// packed bf16x2 fragment images
// QFG: [bh][qt8][ hi:18432 u32 | lo:18432 u32 ]  A-frags [ms8][ks18][lane32][4]
// KFG: [bh][kt32][chunk3]{ hi:[n8][ksl6][lane32][2] | lo same @+3072 }   (24576B/chunk)
// VFG: [bh][kt32][chunk3]{ hi:[ntl12][ks4][lane32][2] | lo @+3072 }      (24576B/chunk)
__device__ __align__(1024) uint32_t QFG[(size_t)32*8*36864];
__device__ __align__(1024) uint32_t KFG[(size_t)32*32*3*6144];
__device__ __align__(1024) uint32_t VFG[(size_t)32*32*3*6144];

__device__ __forceinline__ uint32_t pk2b(float lo, float hi) {
    __nv_bfloat162 h = __floats2bfloat162_rn(lo, hi);
    return *(uint32_t*)&h;
}
__device__ __forceinline__ float bf16res(float x) {
    return x - __bfloat162float(__float2bfloat16_rn(x));
}
#define MMA16(c,a0,a1,a2,a3,b0,b1) \
    asm volatile("mma.sync.aligned.m16n8k16.row.col.f32.bf16.bf16.f32 " \
        "{%0,%1,%2,%3},{%4,%5,%6,%7},{%8,%9},{%0,%1,%2,%3};" \
        : "+f"((c)[0]),"+f"((c)[1]),"+f"((c)[2]),"+f"((c)[3]) \
        : "r"(a0),"r"(a1),"r"(a2),"r"(a3),"r"(b0),"r"(b1))

__device__ __forceinline__ uint32_t smem_u32(const void* p) {
    uint32_t a;
    asm("{ .reg .u64 t; cvta.to.shared.u64 t, %1; cvt.u32.u64 %0, t; }" : "=r"(a) : "l"(p));
    return a;
}
__device__ __forceinline__ void bulkld(uint32_t sdst, const void* gsrc, uint32_t mbar, uint32_t bytes) {
    asm volatile("cp.async.bulk.shared::cluster.global.mbarrier::complete_tx::bytes [%0], [%1], %2, [%3];"
        :: "r"(sdst), "l"(gsrc), "r"(bytes), "r"(mbar) : "memory");
}
#define MB_INIT(mb, c)    asm volatile("mbarrier.init.shared.b64 [%0], %1;" :: "r"(mb), "r"(c) : "memory")
#define MB_EXPECT(mb, nb) asm volatile("mbarrier.arrive.expect_tx.shared.b64 _, [%0], %1;" :: "r"(mb), "r"(nb) : "memory")
#define MB_WAIT(mb, par) do { \
    asm volatile("{\n\t.reg .pred P1;\n\tWL_%=:\n\t" \
        "mbarrier.try_wait.parity.acquire.cta.shared::cta.b64 P1, [%0], %1, 0x989680;\n\t" \
        "@P1 bra.uni WD_%=;\n\tbra.uni WL_%=;\n\tWD_%=:\n\t}" \
        :: "r"(mb), "r"(par) : "memory"); } while (0)

// ============================================================================
// Fused QKV projection: grid (B_*NKV_, 3), 128 threads. y=0:Q, 1:K, 2:V.
// ============================================================================
__global__ void projAll_kernel(
    const float* __restrict__ mv_q,  const float* __restrict__ s_q,
    const float* __restrict__ mv_kv, const float* __restrict__ s_kv,
    const float* __restrict__ wq_mv, const float* __restrict__ wq_s2mv,
    const float* __restrict__ wq_m2s, const float* __restrict__ wq_s2s,
    const float* __restrict__ bq_mv, const float* __restrict__ bq_s,
    const float* __restrict__ wk_mv, const float* __restrict__ wk_s2mv,
    const float* __restrict__ wk_m2s, const float* __restrict__ wk_s2s,
    const float* __restrict__ bk_mv, const float* __restrict__ bk_s,
    const float* __restrict__ wv_mv, const float* __restrict__ wv_s2mv,
    const float* __restrict__ wv_m2s, const float* __restrict__ wv_s2s,
    const float* __restrict__ bv_mv, const float* __restrict__ bv_s)
{
    const int sel = blockIdx.y;
    const int ntok = (sel == 0) ? NQ_ : NKV_;
    if (blockIdx.x >= (unsigned)(B_ * ntok)) return;

    const float* x_mv = (sel == 0) ? mv_q : mv_kv;
    const float* x_s  = (sel == 0) ? s_q  : s_kv;
    const float* w_mv    = (sel == 0) ? wq_mv  : (sel == 1) ? wk_mv  : wv_mv;
    const float* w_s2mv  = (sel == 0) ? wq_s2mv: (sel == 1) ? wk_s2mv: wv_s2mv;
    const float* w_mvs2s = (sel == 0) ? wq_m2s : (sel == 1) ? wk_m2s : wv_m2s;
    const float* w_s2s   = (sel == 0) ? wq_s2s : (sel == 1) ? wk_s2s : wv_s2s;
    const float* b_mv    = (sel == 0) ? bq_mv  : (sel == 1) ? bk_mv  : bv_mv;
    const float* b_s     = (sel == 0) ? bq_s   : (sel == 1) ? bk_s   : bv_s;
    float* out = (sel == 0) ? QB : (sel == 1) ? KB : VB;
    const int applyMetric = (sel == 1);

    __shared__ float xmv[256];
    __shared__ float xs[32];
    const int t = blockIdx.x, b = t / ntok, n = t % ntok, tid = threadIdx.x;
    const float* xp = x_mv + (size_t)t * 256;
    xmv[tid] = xp[tid]; xmv[tid + 128] = xp[tid + 128];
    if (tid < 32) xs[tid] = x_s[(size_t)t * 32 + tid];
    __syncthreads();
    {
        const int o = tid;
        const float* wr = w_mv + o * 80;
        float y[16];
#pragma unroll
        for (int x = 0; x < 16; ++x) {
            float acc = 0.f;
#pragma unroll
            for (int i = 0; i < 16; ++i) acc += xmv[i * 16 + x] * wr[i * 5 + GRADEA[x]];
            y[x] = acc;
        }
        float a0 = b_mv[o];
        const float* ws = w_s2mv + o * 32;
#pragma unroll
        for (int s = 0; s < 32; ++s) a0 += xs[s] * ws[s];
        y[0] += a0;
        const int head = o & 7, hid = o >> 3;
        float* op = out + ((size_t)(b * 8 + head) * ntok + n) * D_ + hid * 16;
#pragma unroll
        for (int x = 0; x < 16; ++x) op[x] = applyMetric ? y[x] * METRICA[x] : y[x];
    }
#pragma unroll
    for (int rr = 0; rr < 2; ++rr) {
        const int o = tid * 2 + rr;
        float y = b_s[o];
        const float* wm = w_mvs2s + o * 16;
#pragma unroll
        for (int i = 0; i < 16; ++i) y += xmv[i * 16] * wm[i];
        const float* ws = w_s2s + o * 32;
#pragma unroll
        for (int s = 0; s < 32; ++s) y += xs[s] * ws[s];
        const int head = o & 7, hid = o >> 3;
        out[((size_t)(b * 8 + head) * ntok + n) * D_ + 256 + hid] = y;
    }
}

// ============================================================================
// repackQ: grid (8, 32), 256 thr. Stage 128x288, emit hi/lo A-frag images.
// ============================================================================
#define STGS 292
__global__ void repackQ_kernel()
{
    extern __shared__ float ss[];
    const int qt = blockIdx.x, bh = blockIdx.y, tid = threadIdx.x;
    const float SCALE = 0.0589255650988789f;   // 1/sqrt(288), folded into Q
    const float* src = QB + ((size_t)bh * NQ_ + qt * 128) * D_;
#pragma unroll
    for (int i = 0; i < 36; ++i) {
        int idx = i * 256 + tid, row = idx / 72, c4 = idx % 72;
        float4 v = *(const float4*)(src + (size_t)row * D_ + c4 * 4);
        float* d = ss + row * STGS + c4 * 4;
        d[0] = v.x; d[1] = v.y; d[2] = v.z; d[3] = v.w;
    }
    __syncthreads();
    uint32_t* dst = QFG + (size_t)(bh * 8 + qt) * 36864;
#pragma unroll
    for (int i = 0; i < 18; ++i) {
        int gidx = i * 256 + tid;            // 0..4607 groups
        int ms = gidx / 576, rem = gidx % 576, ks = rem >> 5, lane = rem & 31;
        int g = lane >> 2, t = lane & 3;
        int r0 = ms * 16 + g, c0 = ks * 16 + 2 * t;
        float v[8];
        v[0] = ss[r0 * STGS + c0] * SCALE;        v[1] = ss[r0 * STGS + c0 + 1] * SCALE;
        v[2] = ss[(r0+8) * STGS + c0] * SCALE;    v[3] = ss[(r0+8) * STGS + c0 + 1] * SCALE;
        v[4] = ss[r0 * STGS + c0 + 8] * SCALE;    v[5] = ss[r0 * STGS + c0 + 9] * SCALE;
        v[6] = ss[(r0+8) * STGS + c0 + 8] * SCALE;v[7] = ss[(r0+8) * STGS + c0 + 9] * SCALE;
        uint4 hi = { pk2b(v[0],v[1]), pk2b(v[2],v[3]), pk2b(v[4],v[5]), pk2b(v[6],v[7]) };
        uint4 lo = { pk2b(bf16res(v[0]),bf16res(v[1])), pk2b(bf16res(v[2]),bf16res(v[3])),
                     pk2b(bf16res(v[4]),bf16res(v[5])), pk2b(bf16res(v[6]),bf16res(v[7])) };
        *(uint4*)(dst + (size_t)gidx * 4)          = hi;
        *(uint4*)(dst + 18432 + (size_t)gidx * 4)  = lo;
    }
}

// ============================================================================
// repackKV: grid (32, 32, 2), 256 thr. z=0: K (B-frags), z=1: V (B-frags, T).
// ============================================================================
__global__ void repackKV_kernel()
{
    extern __shared__ float ss[];
    const int kt = blockIdx.x, bh = blockIdx.y, zv = blockIdx.z, tid = threadIdx.x;
    const float* src = (zv ? VB : KB) + ((size_t)bh * NKV_ + kt * 64) * D_;
#pragma unroll
    for (int i = 0; i < 18; ++i) {
        int idx = i * 256 + tid, row = idx / 72, c4 = idx % 72;
        float4 v = *(const float4*)(src + (size_t)row * D_ + c4 * 4);
        float* d = ss + row * STGS + c4 * 4;
        d[0] = v.x; d[1] = v.y; d[2] = v.z; d[3] = v.w;
    }
    __syncthreads();
    uint32_t* dst = (zv ? VFG : KFG) + (size_t)(bh * 32 + kt) * 3 * 6144;
    if (!zv) {
        // K: hi/lo at [c][n8][ksl6][lane][2]
#pragma unroll
        for (int i = 0; i < 18; ++i) {
            int e = i * 256 + tid;           // 0..4607
            int c = e / 1536, rem = e % 1536;
            int n = rem / 192, rem2 = rem % 192, ksl = rem2 >> 5, lane = rem2 & 31;
            int g = lane >> 2, t = lane & 3;
            int key = n * 8 + g, d0 = c * 96 + ksl * 16 + 2 * t;
            float x0 = ss[key * STGS + d0],     x1 = ss[key * STGS + d0 + 1];
            float x2 = ss[key * STGS + d0 + 8], x3 = ss[key * STGS + d0 + 9];
            uint32_t* ch = dst + (size_t)c * 6144;
            int go = ((n * 6 + ksl) * 32 + lane) * 2;
            *(uint2*)(ch + go)        = make_uint2(pk2b(x0, x1), pk2b(x2, x3));
            *(uint2*)(ch + 3072 + go) = make_uint2(pk2b(bf16res(x0), bf16res(x1)),
                                                   pk2b(bf16res(x2), bf16res(x3)));
        }
    } else {
        // V: hi/lo at [c][ntl12][ks4][lane][2]
#pragma unroll
        for (int i = 0; i < 18; ++i) {
            int e = i * 256 + tid;
            int c = e / 1536, rem = e % 1536;
            int ntl = rem / 128, rem2 = rem % 128, ks = rem2 >> 5, lane = rem2 & 31;
            int g = lane >> 2, t = lane & 3;
            int key0 = ks * 16 + 2 * t, d = c * 96 + ntl * 8 + g;
            float x0 = ss[key0 * STGS + d],       x1 = ss[(key0+1) * STGS + d];
            float x2 = ss[(key0+8) * STGS + d],   x3 = ss[(key0+9) * STGS + d];
            uint32_t* ch = dst + (size_t)c * 6144;
            int go = ((ntl * 4 + ks) * 32 + lane) * 2;
            *(uint2*)(ch + go)        = make_uint2(pk2b(x0, x1), pk2b(x2, x3));
            *(uint2*)(ch + 3072 + go) = make_uint2(pk2b(bf16res(x0), bf16res(x1)),
                                                   pk2b(bf16res(x2), bf16res(x3)));
        }
    }
}

// ============================================================================
// Flash attention: register-resident FA2. grid (8, 32), 256 thr (8 warps).
// Warp w owns q-rows [w*16, w*16+16). smem: Qh|Ql (147456B) + 3x24576B ring.
// ============================================================================
#define SM_BYTES (147456 + 3 * 24576 + 64)

__global__ __launch_bounds__(256, 1) void attn8_kernel()
{
    extern __shared__ uint32_t smu[];
    uint32_t* Qh = smu;                 // 18432 u32
    uint32_t* Ql = smu + 18432;
    uint32_t* bufs[3] = { smu + 36864, smu + 43008, smu + 49152 };

    const int tid = threadIdx.x, bh = blockIdx.y, qt = blockIdx.x;
    const int w = tid >> 5, lane = tid & 31, g = lane >> 2, t = lane & 3;

    const uint32_t sb = smem_u32(smu);
    const uint32_t mbase = sb + (36864 + 3 * 6144) * 4;
    const uint32_t mbQ = mbase + 24;

    const uint32_t* KFb = KFG + (size_t)(bh * 32) * 3 * 6144;
    const uint32_t* VFb = VFG + (size_t)(bh * 32) * 3 * 6144;

    if (tid == 0) {
        MB_INIT(mbase + 0, 1); MB_INIT(mbase + 8, 1); MB_INIT(mbase + 16, 1);
        MB_INIT(mbQ, 1);
    }
    __syncthreads();
    if (tid == 0) {
        MB_EXPECT(mbQ, 147456u);
        bulkld(sb, QFG + (size_t)(bh * 8 + qt) * 36864, mbQ, 147456u);
#pragma unroll
        for (int c = 0; c < 3; ++c) {
            MB_EXPECT(mbase + 8 * c, 24576u);
            bulkld(sb + (36864 + c * 6144) * 4, KFb + c * 6144, mbase + 8 * c, 24576u);
        }
    }

    float O[3][12][4];
#pragma unroll
    for (int c = 0; c < 3; ++c)
#pragma unroll
        for (int n = 0; n < 12; ++n)
#pragma unroll
            for (int k = 0; k < 4; ++k) O[c][n][k] = 0.f;
    float mA = -1e30f, mB = -1e30f, lA = 0.f, lB = 0.f;

    MB_WAIT(mbQ, 0);

    for (int kt = 0; kt < 32; ++kt) {
        const uint32_t* VFt = VFb + (size_t)kt * 3 * 6144;
        const uint32_t* KFn = KFb + (size_t)(kt + 1) * 3 * 6144;

        float cS[8][4];
#pragma unroll
        for (int n = 0; n < 8; ++n)
#pragma unroll
            for (int k = 0; k < 4; ++k) cS[n][k] = 0.f;

        // ---- scores: warp's 16 rows x 64 keys, 3 chunks ----
#pragma unroll
        for (int c = 0; c < 3; ++c) {
            MB_WAIT(mbase + 8 * c, 0);
            const uint32_t* buf = bufs[c];
#pragma unroll
            for (int ksl = 0; ksl < 6; ++ksl) {
                const int ksg = c * 6 + ksl;
                uint4 Ah = *(const uint4*)(Qh + ((w * 18 + ksg) * 32 + lane) * 4);
                uint4 Al = *(const uint4*)(Ql + ((w * 18 + ksg) * 32 + lane) * 4);
#pragma unroll
                for (int n = 0; n < 8; ++n) {
                    uint2 bh2 = *(const uint2*)(buf + ((n * 6 + ksl) * 32 + lane) * 2);
                    uint2 bl2 = *(const uint2*)(buf + 3072 + ((n * 6 + ksl) * 32 + lane) * 2);
                    MMA16(cS[n], Ah.x, Ah.y, Ah.z, Ah.w, bh2.x, bh2.y);
                    MMA16(cS[n], Al.x, Al.y, Al.z, Al.w, bh2.x, bh2.y);
                    MMA16(cS[n], Ah.x, Ah.y, Ah.z, Ah.w, bl2.x, bl2.y);
                }
            }
            __syncthreads();
            if (tid == 0) {
                MB_EXPECT(mbase + 8 * c, 24576u);
                bulkld(sb + (36864 + c * 6144) * 4, VFt + c * 6144, mbase + 8 * c, 24576u);
            }
        }

        // ---- in-register softmax (rows w*16+g and +8) ----
        float mxA = -1e30f, mxB = -1e30f;
#pragma unroll
        for (int n = 0; n < 8; ++n) {
            mxA = fmaxf(mxA, fmaxf(cS[n][0], cS[n][1]));
            mxB = fmaxf(mxB, fmaxf(cS[n][2], cS[n][3]));
        }
        mxA = fmaxf(mxA, __shfl_xor_sync(0xffffffffu, mxA, 1));
        mxA = fmaxf(mxA, __shfl_xor_sync(0xffffffffu, mxA, 2));
        mxB = fmaxf(mxB, __shfl_xor_sync(0xffffffffu, mxB, 1));
        mxB = fmaxf(mxB, __shfl_xor_sync(0xffffffffu, mxB, 2));
        const float mnA = fmaxf(mA, mxA), mnB = fmaxf(mB, mxB);
        const float alA = __expf(mA - mnA), alB = __expf(mB - mnB);
        mA = mnA; mB = mnB;

        uint32_t PhT[8], PhB[8], PlT[8], PlB[8];
        float sA = 0.f, sB = 0.f;
#pragma unroll
        for (int n = 0; n < 8; ++n) {
            float e0 = __expf(cS[n][0] - mnA), e1 = __expf(cS[n][1] - mnA);
            float e2 = __expf(cS[n][2] - mnB), e3 = __expf(cS[n][3] - mnB);
            sA += e0 + e1; sB += e2 + e3;
            PhT[n] = pk2b(e0, e1); PhB[n] = pk2b(e2, e3);
            PlT[n] = pk2b(bf16res(e0), bf16res(e1));
            PlB[n] = pk2b(bf16res(e2), bf16res(e3));
        }
        sA += __shfl_xor_sync(0xffffffffu, sA, 1);
        sA += __shfl_xor_sync(0xffffffffu, sA, 2);
        sB += __shfl_xor_sync(0xffffffffu, sB, 1);
        sB += __shfl_xor_sync(0xffffffffu, sB, 2);
        lA = lA * alA + sA;
        lB = lB * alB + sB;
#pragma unroll
        for (int c = 0; c < 3; ++c)
#pragma unroll
            for (int n = 0; n < 12; ++n) {
                O[c][n][0] *= alA; O[c][n][1] *= alA;
                O[c][n][2] *= alB; O[c][n][3] *= alB;
            }

        // ---- PV: P (regs) x V chunks ----
#pragma unroll
        for (int c = 0; c < 3; ++c) {
            MB_WAIT(mbase + 8 * c, 1);
            const uint32_t* buf = bufs[c];
#pragma unroll
            for (int ks = 0; ks < 4; ++ks) {
                uint32_t ah0 = PhT[2*ks], ah1 = PhB[2*ks], ah2 = PhT[2*ks+1], ah3 = PhB[2*ks+1];
                uint32_t al0 = PlT[2*ks], al1 = PlB[2*ks], al2 = PlT[2*ks+1], al3 = PlB[2*ks+1];
#pragma unroll
                for (int ntl = 0; ntl < 12; ++ntl) {
                    uint2 vh = *(const uint2*)(buf + ((ntl * 4 + ks) * 32 + lane) * 2);
                    uint2 vl = *(const uint2*)(buf + 3072 + ((ntl * 4 + ks) * 32 + lane) * 2);
                    MMA16(O[c][ntl], ah0, ah1, ah2, ah3, vh.x, vh.y);
                    MMA16(O[c][ntl], al0, al1, al2, al3, vh.x, vh.y);
                    MMA16(O[c][ntl], ah0, ah1, ah2, ah3, vl.x, vl.y);
                }
            }
            __syncthreads();
            if (kt < 31 && tid == 0) {
                MB_EXPECT(mbase + 8 * c, 24576u);
                bulkld(sb + (36864 + c * 6144) * 4, KFn + c * 6144, mbase + 8 * c, 24576u);
            }
        }
    }

    // ---- epilogue ----
    const float liA = 1.f / lA, liB = 1.f / lB;
    const int b = bh >> 3, hh = bh & 7;
    const int rA = qt * 128 + w * 16 + g, rB = rA + 8;
    float* oA = OB + (((size_t)(b * NQ_ + rA)) * 8 + hh) * D_;
    float* oB = OB + (((size_t)(b * NQ_ + rB)) * 8 + hh) * D_;
#pragma unroll
    for (int c = 0; c < 3; ++c)
#pragma unroll
        for (int n = 0; n < 12; ++n) {
            int d = c * 96 + n * 8 + 2 * t;
            *(float2*)(oA + d) = make_float2(O[c][n][0] * liA, O[c][n][1] * liA);
            *(float2*)(oB + d) = make_float2(O[c][n][2] * liB, O[c][n][3] * liB);
        }
}

// ============================================================================
// Output projection (unchanged).
// ============================================================================
__global__ void outproj_kernel(const float* __restrict__ wo_mv, const float* __restrict__ wo_s2mv,
                               const float* __restrict__ wo_mvs2s, const float* __restrict__ wo_s2s,
                               const float* __restrict__ bo_mv, const float* __restrict__ bo_s,
                               float* __restrict__ d_out)
{
    __shared__ float xm[2048];
    __shared__ float xsc[256];
    const int t = blockIdx.x, tid = threadIdx.x;
    const float* ob = OB + (size_t)t * 8 * D_;
    for (int idx = tid; idx < 2048; idx += 256) {
        const int c = idx >> 4, x = idx & 15, head = c >> 4, hid = c & 15;
        xm[idx] = ob[head * D_ + hid * 16 + x];
    }
    {
        const int head = tid >> 5, hid = tid & 31;
        xsc[tid] = ob[head * D_ + 256 + hid];
    }
    __syncthreads();
    {
        const int o = tid >> 4, x = tid & 15, gg = GRADE_RT[x];
        const float* wmx = wo_mv + (size_t)o * 128 * 5 + gg;
        float y = 0.f;
#pragma unroll 8
        for (int i = 0; i < 128; ++i) y += xm[i * 16 + x] * wmx[i * 5];
        if (x == 0) {
            float a = bo_mv[o];
            const float* ws = wo_s2mv + o * 256;
#pragma unroll 8
            for (int s = 0; s < 256; ++s) a += xsc[s] * ws[s];
            y += a;
        }
        d_out[(size_t)t * 256 + o * 16 + x] = y;
    }
    if (tid < 32) {
        const int o = tid;
        float y = bo_s[o];
        const float* wm = wo_mvs2s + o * 128;
#pragma unroll 8
        for (int i = 0; i < 128; ++i) y += xm[i * 16] * wm[i];
        const float* ws = wo_s2s + o * 256;
#pragma unroll 8
        for (int s = 0; s < 256; ++s) y += xsc[s] * ws[s];
        d_out[(size_t)B_ * NQ_ * 256 + (size_t)t * 32 + o] = y;
    }
}

extern "C" void kernel_launch(void* const* d_in, const int* in_sizes, int n_in,
                              void* d_out, int out_size)
{
    (void)in_sizes; (void)n_in; (void)out_size;
    const float* mv_kv = (const float*)d_in[0];
    const float* mv_q  = (const float*)d_in[1];
    const float* s_kv  = (const float*)d_in[2];
    const float* s_q   = (const float*)d_in[3];
    const float* wq_mv = (const float*)d_in[4],  *wq_s2mv = (const float*)d_in[5];
    const float* wq_m2s = (const float*)d_in[6], *wq_s2s = (const float*)d_in[7];
    const float* bq_mv = (const float*)d_in[8],  *bq_s = (const float*)d_in[9];
    const float* wk_mv = (const float*)d_in[10], *wk_s2mv = (const float*)d_in[11];
    const float* wk_m2s = (const float*)d_in[12],*wk_s2s = (const float*)d_in[13];
    const float* bk_mv = (const float*)d_in[14], *bk_s = (const float*)d_in[15];
    const float* wv_mv = (const float*)d_in[16], *wv_s2mv = (const float*)d_in[17];
    const float* wv_m2s = (const float*)d_in[18],*wv_s2s = (const float*)d_in[19];
    const float* bv_mv = (const float*)d_in[20], *bv_s = (const float*)d_in[21];
    const float* wo_mv = (const float*)d_in[22], *wo_s2mv = (const float*)d_in[23];
    const float* wo_m2s = (const float*)d_in[24],*wo_s2s = (const float*)d_in[25];
    const float* bo_mv = (const float*)d_in[26], *bo_s = (const float*)d_in[27];

    const int stageQ = 128 * STGS * sizeof(float);   // 149,504B
    const int stageKV = 64 * STGS * sizeof(float);
    cudaFuncSetAttribute(repackQ_kernel, cudaFuncAttributeMaxDynamicSharedMemorySize, stageQ);
    cudaFuncSetAttribute(repackKV_kernel, cudaFuncAttributeMaxDynamicSharedMemorySize, stageKV);
    cudaFuncSetAttribute(attn8_kernel, cudaFuncAttributeMaxDynamicSharedMemorySize, SM_BYTES);

    // launch order fixed so attn lands at capture index 3
    projAll_kernel<<<dim3(B_ * NKV_, 3), 128>>>(
        mv_q, s_q, mv_kv, s_kv,
        wq_mv, wq_s2mv, wq_m2s, wq_s2s, bq_mv, bq_s,
        wk_mv, wk_s2mv, wk_m2s, wk_s2s, bk_mv, bk_s,
        wv_mv, wv_s2mv, wv_m2s, wv_s2s, bv_mv, bv_s);
    repackQ_kernel<<<dim3(8, 32), 256, stageQ>>>();
    repackKV_kernel<<<dim3(32, 32, 2), 256, stageKV>>>();
    attn8_kernel<<<dim3(8, 32), 256, SM_BYTES>>>();
    outproj_kernel<<<B_ * NQ_, 256>>>(wo_mv, wo_s2mv, wo_m2s, wo_s2s, bo_mv, bo_s, (float*)d_out);
}

// round 10
// speedup vs baseline: 2.2276x; 1.9401x over previous
#include <cuda_runtime.h>
#include <cuda_bf16.h>
#include <math.h>
#include <stdint.h>

#define B_    4
#define NQ_   1024
#define NKV_  2048
#define D_    288

__device__ constexpr int   GRADEA[16] = {0,1,1,1,1,2,2,2,2,2,2,3,3,3,3,4};
__device__ constexpr float METRICA[16] = {1.f,1.f,-1.f,-1.f,-1.f,-1.f,-1.f,-1.f,
                                          1.f,1.f, 1.f, 1.f, 1.f, 1.f,-1.f,-1.f};
__constant__ int GRADE_RT[16] = {0,1,1,1,1,2,2,2,2,2,2,3,3,3,3,4};

// scratch
__device__ __align__(1024) float QB[(size_t)B_*8*NQ_*D_];
__device__ __align__(1024) float KB[(size_t)B_*8*NKV_*D_];
__device__ __align__(1024) float VB[(size_t)B_*8*NKV_*D_];
__device__ __align__(1024) float OB[(size_t)B_*NQ_*8*D_];
// packed bf16x2 fragment images (unchanged from R9)
__device__ __align__(1024) uint32_t QFG[(size_t)32*8*36864];
__device__ __align__(1024) uint32_t KFG[(size_t)32*32*3*6144];
__device__ __align__(1024) uint32_t VFG[(size_t)32*32*3*6144];

__device__ __forceinline__ uint32_t pk2b(float lo, float hi) {
    __nv_bfloat162 h = __floats2bfloat162_rn(lo, hi);
    return *(uint32_t*)&h;
}
__device__ __forceinline__ float bf16res(float x) {
    return x - __bfloat162float(__float2bfloat16_rn(x));
}
#define MMA16(c,a0,a1,a2,a3,b0,b1) \
    asm volatile("mma.sync.aligned.m16n8k16.row.col.f32.bf16.bf16.f32 " \
        "{%0,%1,%2,%3},{%4,%5,%6,%7},{%8,%9},{%0,%1,%2,%3};" \
        : "+f"((c)[0]),"+f"((c)[1]),"+f"((c)[2]),"+f"((c)[3]) \
        : "r"(a0),"r"(a1),"r"(a2),"r"(a3),"r"(b0),"r"(b1))

__device__ __forceinline__ uint32_t smem_u32(const void* p) {
    uint32_t a;
    asm("{ .reg .u64 t; cvta.to.shared.u64 t, %1; cvt.u32.u64 %0, t; }" : "=r"(a) : "l"(p));
    return a;
}
__device__ __forceinline__ void bulkld(uint32_t sdst, const void* gsrc, uint32_t mbar, uint32_t bytes) {
    asm volatile("cp.async.bulk.shared::cluster.global.mbarrier::complete_tx::bytes [%0], [%1], %2, [%3];"
        :: "r"(sdst), "l"(gsrc), "r"(bytes), "r"(mbar) : "memory");
}
#define MB_INIT(mb, c)    asm volatile("mbarrier.init.shared.b64 [%0], %1;" :: "r"(mb), "r"(c) : "memory")
#define MB_EXPECT(mb, nb) asm volatile("mbarrier.arrive.expect_tx.shared.b64 _, [%0], %1;" :: "r"(mb), "r"(nb) : "memory")
#define MB_WAIT(mb, par) do { \
    asm volatile("{\n\t.reg .pred P1;\n\tWL_%=:\n\t" \
        "mbarrier.try_wait.parity.acquire.cta.shared::cta.b64 P1, [%0], %1, 0x989680;\n\t" \
        "@P1 bra.uni WD_%=;\n\tbra.uni WL_%=;\n\tWD_%=:\n\t}" \
        :: "r"(mb), "r"(par) : "memory"); } while (0)

// ============================================================================
// proj2: token-per-lane, channels-per-warp. grid (256, 3), 128 threads.
// y: 0=Q, 1=K(+metric), 2=V. Tile = 32 tokens. Weight LDGs are warp-uniform.
// ============================================================================
__global__ void proj2_kernel(
    const float* __restrict__ mv_q,  const float* __restrict__ s_q,
    const float* __restrict__ mv_kv, const float* __restrict__ s_kv,
    const float* __restrict__ wq_mv, const float* __restrict__ wq_s2mv,
    const float* __restrict__ wq_m2s, const float* __restrict__ wq_s2s,
    const float* __restrict__ bq_mv, const float* __restrict__ bq_s,
    const float* __restrict__ wk_mv, const float* __restrict__ wk_s2mv,
    const float* __restrict__ wk_m2s, const float* __restrict__ wk_s2s,
    const float* __restrict__ bk_mv, const float* __restrict__ bk_s,
    const float* __restrict__ wv_mv, const float* __restrict__ wv_s2mv,
    const float* __restrict__ wv_m2s, const float* __restrict__ wv_s2s,
    const float* __restrict__ bv_mv, const float* __restrict__ bv_s)
{
    __shared__ float xT[256 * 33];   // [feat][tok], stride 33 (conflict-free by lane)
    __shared__ float xsT[32 * 33];   // [s][tok]

    const int sel = blockIdx.y;
    const int ntok = (sel == 0) ? NQ_ : NKV_;
    const int ntiles = (B_ * ntok) / 32;
    const int tile = blockIdx.x;
    if (tile >= ntiles) return;

    const float* x_mv = (sel == 0) ? mv_q : mv_kv;
    const float* x_s  = (sel == 0) ? s_q  : s_kv;
    const float* w_mv    = (sel == 0) ? wq_mv  : (sel == 1) ? wk_mv  : wv_mv;
    const float* w_s2mv  = (sel == 0) ? wq_s2mv: (sel == 1) ? wk_s2mv: wv_s2mv;
    const float* w_mvs2s = (sel == 0) ? wq_m2s : (sel == 1) ? wk_m2s : wv_m2s;
    const float* w_s2s   = (sel == 0) ? wq_s2s : (sel == 1) ? wk_s2s : wv_s2s;
    const float* b_mv    = (sel == 0) ? bq_mv  : (sel == 1) ? bk_mv  : bv_mv;
    const float* b_s     = (sel == 0) ? bq_s   : (sel == 1) ? bk_s   : bv_s;
    float* out = (sel == 0) ? QB : (sel == 1) ? KB : VB;
    const int applyMetric = (sel == 1);

    const int tid = threadIdx.x, w = tid >> 5, lane = tid & 31;
    const int t0 = tile * 32;                // global token base
    const int b = t0 / ntok, n0 = t0 % ntok;

    // stage x (coalesced read, transposed write)
    {
        const float4* src = (const float4*)(x_mv + (size_t)t0 * 256);
#pragma unroll
        for (int i = 0; i < 16; ++i) {
            int f4 = i * 128 + tid;          // 0..2047
            int tok = f4 >> 6, feat4 = f4 & 63;
            float4 v = src[f4];
            xT[(feat4 * 4 + 0) * 33 + tok] = v.x;
            xT[(feat4 * 4 + 1) * 33 + tok] = v.y;
            xT[(feat4 * 4 + 2) * 33 + tok] = v.z;
            xT[(feat4 * 4 + 3) * 33 + tok] = v.w;
        }
        const float* ssrc = x_s + (size_t)t0 * 32;
#pragma unroll
        for (int i = 0; i < 8; ++i) {
            int idx = i * 128 + tid;         // 0..1023
            int tok = idx >> 5, s = idx & 31;
            xsT[s * 33 + tok] = ssrc[tok * 32 + s];
        }
    }
    __syncthreads();

    // mv outputs: warp w handles channels [w*32, w*32+32)
    for (int oc = 0; oc < 32; ++oc) {
        const int o = w * 32 + oc;
        const float* wr = w_mv + o * 80;           // warp-uniform
        float a0 = b_mv[o];
        const float* ws = w_s2mv + o * 32;
#pragma unroll
        for (int s = 0; s < 32; ++s) a0 += xsT[s * 33 + lane] * ws[s];

        const int head = o & 7, hid = o >> 3;
        float* op = out + ((size_t)(b * 8 + head) * ntok + (n0 + lane)) * D_ + hid * 16;
#pragma unroll
        for (int x = 0; x < 16; ++x) {
            float acc = (x == 0) ? a0 : 0.f;
            const int g = GRADEA[x];
#pragma unroll
            for (int i = 0; i < 16; ++i)
                acc += xT[(i * 16 + x) * 33 + lane] * wr[i * 5 + g];
            op[x] = applyMetric ? acc * METRICA[x] : acc;
        }
    }

    // scalar outputs: warp w handles channels [w*64, w*64+64)
    for (int oc = 0; oc < 64; ++oc) {
        const int o = w * 64 + oc;
        float y = b_s[o];
        const float* wm = w_mvs2s + o * 16;
#pragma unroll
        for (int i = 0; i < 16; ++i) y += xT[(i * 16) * 33 + lane] * wm[i];
        const float* ws = w_s2s + o * 32;
#pragma unroll
        for (int s = 0; s < 32; ++s) y += xsT[s * 33 + lane] * ws[s];
        const int head = o & 7, hid = o >> 3;
        out[((size_t)(b * 8 + head) * ntok + (n0 + lane)) * D_ + 256 + hid] = y;
    }
}

// ============================================================================
// repackQ: grid (8, 32), 256 thr (unchanged from R9).
// ============================================================================
#define STGS 292
__global__ void repackQ_kernel()
{
    extern __shared__ float ss[];
    const int qt = blockIdx.x, bh = blockIdx.y, tid = threadIdx.x;
    const float SCALE = 0.0589255650988789f;
    const float* src = QB + ((size_t)bh * NQ_ + qt * 128) * D_;
#pragma unroll
    for (int i = 0; i < 36; ++i) {
        int idx = i * 256 + tid, row = idx / 72, c4 = idx % 72;
        float4 v = *(const float4*)(src + (size_t)row * D_ + c4 * 4);
        float* d = ss + row * STGS + c4 * 4;
        d[0] = v.x; d[1] = v.y; d[2] = v.z; d[3] = v.w;
    }
    __syncthreads();
    uint32_t* dst = QFG + (size_t)(bh * 8 + qt) * 36864;
#pragma unroll
    for (int i = 0; i < 18; ++i) {
        int gidx = i * 256 + tid;
        int ms = gidx / 576, rem = gidx % 576, ks = rem >> 5, lane = rem & 31;
        int g = lane >> 2, t = lane & 3;
        int r0 = ms * 16 + g, c0 = ks * 16 + 2 * t;
        float v[8];
        v[0] = ss[r0 * STGS + c0] * SCALE;        v[1] = ss[r0 * STGS + c0 + 1] * SCALE;
        v[2] = ss[(r0+8) * STGS + c0] * SCALE;    v[3] = ss[(r0+8) * STGS + c0 + 1] * SCALE;
        v[4] = ss[r0 * STGS + c0 + 8] * SCALE;    v[5] = ss[r0 * STGS + c0 + 9] * SCALE;
        v[6] = ss[(r0+8) * STGS + c0 + 8] * SCALE;v[7] = ss[(r0+8) * STGS + c0 + 9] * SCALE;
        uint4 hi = { pk2b(v[0],v[1]), pk2b(v[2],v[3]), pk2b(v[4],v[5]), pk2b(v[6],v[7]) };
        uint4 lo = { pk2b(bf16res(v[0]),bf16res(v[1])), pk2b(bf16res(v[2]),bf16res(v[3])),
                     pk2b(bf16res(v[4]),bf16res(v[5])), pk2b(bf16res(v[6]),bf16res(v[7])) };
        *(uint4*)(dst + (size_t)gidx * 4)          = hi;
        *(uint4*)(dst + 18432 + (size_t)gidx * 4)  = lo;
    }
}

// ============================================================================
// repackKV: grid (32, 32, 2), 256 thr (unchanged from R9).
// ============================================================================
__global__ void repackKV_kernel()
{
    extern __shared__ float ss[];
    const int kt = blockIdx.x, bh = blockIdx.y, zv = blockIdx.z, tid = threadIdx.x;
    const float* src = (zv ? VB : KB) + ((size_t)bh * NKV_ + kt * 64) * D_;
#pragma unroll
    for (int i = 0; i < 18; ++i) {
        int idx = i * 256 + tid, row = idx / 72, c4 = idx % 72;
        float4 v = *(const float4*)(src + (size_t)row * D_ + c4 * 4);
        float* d = ss + row * STGS + c4 * 4;
        d[0] = v.x; d[1] = v.y; d[2] = v.z; d[3] = v.w;
    }
    __syncthreads();
    uint32_t* dst = (zv ? VFG : KFG) + (size_t)(bh * 32 + kt) * 3 * 6144;
    if (!zv) {
#pragma unroll
        for (int i = 0; i < 18; ++i) {
            int e = i * 256 + tid;
            int c = e / 1536, rem = e % 1536;
            int n = rem / 192, rem2 = rem % 192, ksl = rem2 >> 5, lane = rem2 & 31;
            int g = lane >> 2, t = lane & 3;
            int key = n * 8 + g, d0 = c * 96 + ksl * 16 + 2 * t;
            float x0 = ss[key * STGS + d0],     x1 = ss[key * STGS + d0 + 1];
            float x2 = ss[key * STGS + d0 + 8], x3 = ss[key * STGS + d0 + 9];
            uint32_t* ch = dst + (size_t)c * 6144;
            int go = ((n * 6 + ksl) * 32 + lane) * 2;
            *(uint2*)(ch + go)        = make_uint2(pk2b(x0, x1), pk2b(x2, x3));
            *(uint2*)(ch + 3072 + go) = make_uint2(pk2b(bf16res(x0), bf16res(x1)),
                                                   pk2b(bf16res(x2), bf16res(x3)));
        }
    } else {
#pragma unroll
        for (int i = 0; i < 18; ++i) {
            int e = i * 256 + tid;
            int c = e / 1536, rem = e % 1536;
            int ntl = rem / 128, rem2 = rem % 128, ks = rem2 >> 5, lane = rem2 & 31;
            int g = lane >> 2, t = lane & 3;
            int key0 = ks * 16 + 2 * t, d = c * 96 + ntl * 8 + g;
            float x0 = ss[key0 * STGS + d],       x1 = ss[(key0+1) * STGS + d];
            float x2 = ss[(key0+8) * STGS + d],   x3 = ss[(key0+9) * STGS + d];
            uint32_t* ch = dst + (size_t)c * 6144;
            int go = ((ntl * 4 + ks) * 32 + lane) * 2;
            *(uint2*)(ch + go)        = make_uint2(pk2b(x0, x1), pk2b(x2, x3));
            *(uint2*)(ch + 3072 + go) = make_uint2(pk2b(bf16res(x0), bf16res(x1)),
                                                   pk2b(bf16res(x2), bf16res(x3)));
        }
    }
}

// ============================================================================
// attn8: register-resident FA2, split-bf16 (unchanged from R9).
// ============================================================================
#define SM_BYTES (147456 + 3 * 24576 + 64)

__global__ __launch_bounds__(256, 1) void attn8_kernel()
{
    extern __shared__ uint32_t smu[];
    uint32_t* Qh = smu;
    uint32_t* Ql = smu + 18432;
    uint32_t* bufs[3] = { smu + 36864, smu + 43008, smu + 49152 };

    const int tid = threadIdx.x, bh = blockIdx.y, qt = blockIdx.x;
    const int w = tid >> 5, lane = tid & 31, g = lane >> 2, t = lane & 3;

    const uint32_t sb = smem_u32(smu);
    const uint32_t mbase = sb + (36864 + 3 * 6144) * 4;
    const uint32_t mbQ = mbase + 24;

    const uint32_t* KFb = KFG + (size_t)(bh * 32) * 3 * 6144;
    const uint32_t* VFb = VFG + (size_t)(bh * 32) * 3 * 6144;

    if (tid == 0) {
        MB_INIT(mbase + 0, 1); MB_INIT(mbase + 8, 1); MB_INIT(mbase + 16, 1);
        MB_INIT(mbQ, 1);
    }
    __syncthreads();
    if (tid == 0) {
        MB_EXPECT(mbQ, 147456u);
        bulkld(sb, QFG + (size_t)(bh * 8 + qt) * 36864, mbQ, 147456u);
#pragma unroll
        for (int c = 0; c < 3; ++c) {
            MB_EXPECT(mbase + 8 * c, 24576u);
            bulkld(sb + (36864 + c * 6144) * 4, KFb + c * 6144, mbase + 8 * c, 24576u);
        }
    }

    float O[3][12][4];
#pragma unroll
    for (int c = 0; c < 3; ++c)
#pragma unroll
        for (int n = 0; n < 12; ++n)
#pragma unroll
            for (int k = 0; k < 4; ++k) O[c][n][k] = 0.f;
    float mA = -1e30f, mB = -1e30f, lA = 0.f, lB = 0.f;

    MB_WAIT(mbQ, 0);

    for (int kt = 0; kt < 32; ++kt) {
        const uint32_t* VFt = VFb + (size_t)kt * 3 * 6144;
        const uint32_t* KFn = KFb + (size_t)(kt + 1) * 3 * 6144;

        float cS[8][4];
#pragma unroll
        for (int n = 0; n < 8; ++n)
#pragma unroll
            for (int k = 0; k < 4; ++k) cS[n][k] = 0.f;

#pragma unroll
        for (int c = 0; c < 3; ++c) {
            MB_WAIT(mbase + 8 * c, 0);
            const uint32_t* buf = bufs[c];
#pragma unroll
            for (int ksl = 0; ksl < 6; ++ksl) {
                const int ksg = c * 6 + ksl;
                uint4 Ah = *(const uint4*)(Qh + ((w * 18 + ksg) * 32 + lane) * 4);
                uint4 Al = *(const uint4*)(Ql + ((w * 18 + ksg) * 32 + lane) * 4);
#pragma unroll
                for (int n = 0; n < 8; ++n) {
                    uint2 bh2 = *(const uint2*)(buf + ((n * 6 + ksl) * 32 + lane) * 2);
                    uint2 bl2 = *(const uint2*)(buf + 3072 + ((n * 6 + ksl) * 32 + lane) * 2);
                    MMA16(cS[n], Ah.x, Ah.y, Ah.z, Ah.w, bh2.x, bh2.y);
                    MMA16(cS[n], Al.x, Al.y, Al.z, Al.w, bh2.x, bh2.y);
                    MMA16(cS[n], Ah.x, Ah.y, Ah.z, Ah.w, bl2.x, bl2.y);
                }
            }
            __syncthreads();
            if (tid == 0) {
                MB_EXPECT(mbase + 8 * c, 24576u);
                bulkld(sb + (36864 + c * 6144) * 4, VFt + c * 6144, mbase + 8 * c, 24576u);
            }
        }

        float mxA = -1e30f, mxB = -1e30f;
#pragma unroll
        for (int n = 0; n < 8; ++n) {
            mxA = fmaxf(mxA, fmaxf(cS[n][0], cS[n][1]));
            mxB = fmaxf(mxB, fmaxf(cS[n][2], cS[n][3]));
        }
        mxA = fmaxf(mxA, __shfl_xor_sync(0xffffffffu, mxA, 1));
        mxA = fmaxf(mxA, __shfl_xor_sync(0xffffffffu, mxA, 2));
        mxB = fmaxf(mxB, __shfl_xor_sync(0xffffffffu, mxB, 1));
        mxB = fmaxf(mxB, __shfl_xor_sync(0xffffffffu, mxB, 2));
        const float mnA = fmaxf(mA, mxA), mnB = fmaxf(mB, mxB);
        const float alA = __expf(mA - mnA), alB = __expf(mB - mnB);
        mA = mnA; mB = mnB;

        uint32_t PhT[8], PhB[8], PlT[8], PlB[8];
        float sA = 0.f, sB = 0.f;
#pragma unroll
        for (int n = 0; n < 8; ++n) {
            float e0 = __expf(cS[n][0] - mnA), e1 = __expf(cS[n][1] - mnA);
            float e2 = __expf(cS[n][2] - mnB), e3 = __expf(cS[n][3] - mnB);
            sA += e0 + e1; sB += e2 + e3;
            PhT[n] = pk2b(e0, e1); PhB[n] = pk2b(e2, e3);
            PlT[n] = pk2b(bf16res(e0), bf16res(e1));
            PlB[n] = pk2b(bf16res(e2), bf16res(e3));
        }
        sA += __shfl_xor_sync(0xffffffffu, sA, 1);
        sA += __shfl_xor_sync(0xffffffffu, sA, 2);
        sB += __shfl_xor_sync(0xffffffffu, sB, 1);
        sB += __shfl_xor_sync(0xffffffffu, sB, 2);
        lA = lA * alA + sA;
        lB = lB * alB + sB;
#pragma unroll
        for (int c = 0; c < 3; ++c)
#pragma unroll
            for (int n = 0; n < 12; ++n) {
                O[c][n][0] *= alA; O[c][n][1] *= alA;
                O[c][n][2] *= alB; O[c][n][3] *= alB;
            }

#pragma unroll
        for (int c = 0; c < 3; ++c) {
            MB_WAIT(mbase + 8 * c, 1);
            const uint32_t* buf = bufs[c];
#pragma unroll
            for (int ks = 0; ks < 4; ++ks) {
                uint32_t ah0 = PhT[2*ks], ah1 = PhB[2*ks], ah2 = PhT[2*ks+1], ah3 = PhB[2*ks+1];
                uint32_t al0 = PlT[2*ks], al1 = PlB[2*ks], al2 = PlT[2*ks+1], al3 = PlB[2*ks+1];
#pragma unroll
                for (int ntl = 0; ntl < 12; ++ntl) {
                    uint2 vh = *(const uint2*)(buf + ((ntl * 4 + ks) * 32 + lane) * 2);
                    uint2 vl = *(const uint2*)(buf + 3072 + ((ntl * 4 + ks) * 32 + lane) * 2);
                    MMA16(O[c][ntl], ah0, ah1, ah2, ah3, vh.x, vh.y);
                    MMA16(O[c][ntl], al0, al1, al2, al3, vh.x, vh.y);
                    MMA16(O[c][ntl], ah0, ah1, ah2, ah3, vl.x, vl.y);
                }
            }
            __syncthreads();
            if (kt < 31 && tid == 0) {
                MB_EXPECT(mbase + 8 * c, 24576u);
                bulkld(sb + (36864 + c * 6144) * 4, KFn + c * 6144, mbase + 8 * c, 24576u);
            }
        }
    }

    const float liA = 1.f / lA, liB = 1.f / lB;
    const int b = bh >> 3, hh = bh & 7;
    const int rA = qt * 128 + w * 16 + g, rB = rA + 8;
    float* oA = OB + (((size_t)(b * NQ_ + rA)) * 8 + hh) * D_;
    float* oB = OB + (((size_t)(b * NQ_ + rB)) * 8 + hh) * D_;
#pragma unroll
    for (int c = 0; c < 3; ++c)
#pragma unroll
        for (int n = 0; n < 12; ++n) {
            int d = c * 96 + n * 8 + 2 * t;
            *(float2*)(oA + d) = make_float2(O[c][n][0] * liA, O[c][n][1] * liA);
            *(float2*)(oB + d) = make_float2(O[c][n][2] * liB, O[c][n][3] * liB);
        }
}

// ============================================================================
// Output projection (unchanged).
// ============================================================================
__global__ void outproj_kernel(const float* __restrict__ wo_mv, const float* __restrict__ wo_s2mv,
                               const float* __restrict__ wo_mvs2s, const float* __restrict__ wo_s2s,
                               const float* __restrict__ bo_mv, const float* __restrict__ bo_s,
                               float* __restrict__ d_out)
{
    __shared__ float xm[2048];
    __shared__ float xsc[256];
    const int t = blockIdx.x, tid = threadIdx.x;
    const float* ob = OB + (size_t)t * 8 * D_;
    for (int idx = tid; idx < 2048; idx += 256) {
        const int c = idx >> 4, x = idx & 15, head = c >> 4, hid = c & 15;
        xm[idx] = ob[head * D_ + hid * 16 + x];
    }
    {
        const int head = tid >> 5, hid = tid & 31;
        xsc[tid] = ob[head * D_ + 256 + hid];
    }
    __syncthreads();
    {
        const int o = tid >> 4, x = tid & 15, gg = GRADE_RT[x];
        const float* wmx = wo_mv + (size_t)o * 128 * 5 + gg;
        float y = 0.f;
#pragma unroll 8
        for (int i = 0; i < 128; ++i) y += xm[i * 16 + x] * wmx[i * 5];
        if (x == 0) {
            float a = bo_mv[o];
            const float* ws = wo_s2mv + o * 256;
#pragma unroll 8
            for (int s = 0; s < 256; ++s) a += xsc[s] * ws[s];
            y += a;
        }
        d_out[(size_t)t * 256 + o * 16 + x] = y;
    }
    if (tid < 32) {
        const int o = tid;
        float y = bo_s[o];
        const float* wm = wo_mvs2s + o * 128;
#pragma unroll 8
        for (int i = 0; i < 128; ++i) y += xm[i * 16] * wm[i];
        const float* ws = wo_s2s + o * 256;
#pragma unroll 8
        for (int s = 0; s < 256; ++s) y += xsc[s] * ws[s];
        d_out[(size_t)B_ * NQ_ * 256 + (size_t)t * 32 + o] = y;
    }
}

extern "C" void kernel_launch(void* const* d_in, const int* in_sizes, int n_in,
                              void* d_out, int out_size)
{
    (void)in_sizes; (void)n_in; (void)out_size;
    const float* mv_kv = (const float*)d_in[0];
    const float* mv_q  = (const float*)d_in[1];
    const float* s_kv  = (const float*)d_in[2];
    const float* s_q   = (const float*)d_in[3];
    const float* wq_mv = (const float*)d_in[4],  *wq_s2mv = (const float*)d_in[5];
    const float* wq_m2s = (const float*)d_in[6], *wq_s2s = (const float*)d_in[7];
    const float* bq_mv = (const float*)d_in[8],  *bq_s = (const float*)d_in[9];
    const float* wk_mv = (const float*)d_in[10], *wk_s2mv = (const float*)d_in[11];
    const float* wk_m2s = (const float*)d_in[12],*wk_s2s = (const float*)d_in[13];
    const float* bk_mv = (const float*)d_in[14], *bk_s = (const float*)d_in[15];
    const float* wv_mv = (const float*)d_in[16], *wv_s2mv = (const float*)d_in[17];
    const float* wv_m2s = (const float*)d_in[18],*wv_s2s = (const float*)d_in[19];
    const float* bv_mv = (const float*)d_in[20], *bv_s = (const float*)d_in[21];
    const float* wo_mv = (const float*)d_in[22], *wo_s2mv = (const float*)d_in[23];
    const float* wo_m2s = (const float*)d_in[24],*wo_s2s = (const float*)d_in[25];
    const float* bo_mv = (const float*)d_in[26], *bo_s = (const float*)d_in[27];

    const int stageQ = 128 * STGS * sizeof(float);
    const int stageKV = 64 * STGS * sizeof(float);
    cudaFuncSetAttribute(repackQ_kernel, cudaFuncAttributeMaxDynamicSharedMemorySize, stageQ);
    cudaFuncSetAttribute(repackKV_kernel, cudaFuncAttributeMaxDynamicSharedMemorySize, stageKV);
    cudaFuncSetAttribute(attn8_kernel, cudaFuncAttributeMaxDynamicSharedMemorySize, SM_BYTES);

    proj2_kernel<<<dim3(256, 3), 128>>>(
        mv_q, s_q, mv_kv, s_kv,
        wq_mv, wq_s2mv, wq_m2s, wq_s2s, bq_mv, bq_s,
        wk_mv, wk_s2mv, wk_m2s, wk_s2s, bk_mv, bk_s,
        wv_mv, wv_s2mv, wv_m2s, wv_s2s, bv_mv, bv_s);
    repackQ_kernel<<<dim3(8, 32), 256, stageQ>>>();
    repackKV_kernel<<<dim3(32, 32, 2), 256, stageKV>>>();
    attn8_kernel<<<dim3(8, 32), 256, SM_BYTES>>>();
    outproj_kernel<<<B_ * NQ_, 256>>>(wo_mv, wo_s2mv, wo_m2s, wo_s2s, bo_mv, bo_s, (float*)d_out);
}

// round 13
// speedup vs baseline: 2.4716x; 1.1095x over previous
#include <cuda_runtime.h>
#include <cuda_bf16.h>
#include <math.h>
#include <stdint.h>

#define B_    4
#define NQ_   1024
#define NKV_  2048
#define D_    288

__device__ constexpr int   GRADEA[16] = {0,1,1,1,1,2,2,2,2,2,2,3,3,3,3,4};
__device__ constexpr float METRICA[16] = {1.f,1.f,-1.f,-1.f,-1.f,-1.f,-1.f,-1.f,
                                          1.f,1.f, 1.f, 1.f, 1.f, 1.f,-1.f,-1.f};
__constant__ int GRADE_RT[16] = {0,1,1,1,1,2,2,2,2,2,2,3,3,3,3,4};

// scratch
__device__ __align__(1024) float QB[(size_t)B_*8*NQ_*D_];
__device__ __align__(1024) float KB[(size_t)B_*8*NKV_*D_];
__device__ __align__(1024) float VB[(size_t)B_*8*NKV_*D_];
__device__ __align__(1024) float OB[(size_t)B_*NQ_*8*D_];
// packed bf16x2 fragment images
__device__ __align__(1024) uint32_t QFG[(size_t)32*8*36864];
__device__ __align__(1024) uint32_t KFG[(size_t)32*32*3*6144];
__device__ __align__(1024) uint32_t VFG[(size_t)32*32*3*6144];

__device__ __forceinline__ uint32_t pk2b(float lo, float hi) {
    __nv_bfloat162 h = __floats2bfloat162_rn(lo, hi);
    return *(uint32_t*)&h;
}
__device__ __forceinline__ float bf16res(float x) {
    return x - __bfloat162float(__float2bfloat16_rn(x));
}
#define MMA16(c,a0,a1,a2,a3,b0,b1) \
    asm volatile("mma.sync.aligned.m16n8k16.row.col.f32.bf16.bf16.f32 " \
        "{%0,%1,%2,%3},{%4,%5,%6,%7},{%8,%9},{%0,%1,%2,%3};" \
        : "+f"((c)[0]),"+f"((c)[1]),"+f"((c)[2]),"+f"((c)[3]) \
        : "r"(a0),"r"(a1),"r"(a2),"r"(a3),"r"(b0),"r"(b1))

__device__ __forceinline__ uint32_t smem_u32(const void* p) {
    uint32_t a;
    asm("{ .reg .u64 t; cvta.to.shared.u64 t, %1; cvt.u32.u64 %0, t; }" : "=r"(a) : "l"(p));
    return a;
}
__device__ __forceinline__ void bulkld(uint32_t sdst, const void* gsrc, uint32_t mbar, uint32_t bytes) {
    asm volatile("cp.async.bulk.shared::cluster.global.mbarrier::complete_tx::bytes [%0], [%1], %2, [%3];"
        :: "r"(sdst), "l"(gsrc), "r"(bytes), "r"(mbar) : "memory");
}
#define MB_INIT(mb, c)    asm volatile("mbarrier.init.shared.b64 [%0], %1;" :: "r"(mb), "r"(c) : "memory")
#define MB_EXPECT(mb, nb) asm volatile("mbarrier.arrive.expect_tx.shared.b64 _, [%0], %1;" :: "r"(mb), "r"(nb) : "memory")
#define MB_WAIT(mb, par) do { \
    asm volatile("{\n\t.reg .pred P1;\n\tWL_%=:\n\t" \
        "mbarrier.try_wait.parity.acquire.cta.shared::cta.b64 P1, [%0], %1, 0x989680;\n\t" \
        "@P1 bra.uni WD_%=;\n\tbra.uni WL_%=;\n\tWD_%=:\n\t}" \
        :: "r"(mb), "r"(par) : "memory"); } while (0)

// ============================================================================
// proj2: token-per-lane, channels-per-warp. grid (256, 3), 128 threads.
// ============================================================================
__global__ void proj2_kernel(
    const float* __restrict__ mv_q,  const float* __restrict__ s_q,
    const float* __restrict__ mv_kv, const float* __restrict__ s_kv,
    const float* __restrict__ wq_mv, const float* __restrict__ wq_s2mv,
    const float* __restrict__ wq_m2s, const float* __restrict__ wq_s2s,
    const float* __restrict__ bq_mv, const float* __restrict__ bq_s,
    const float* __restrict__ wk_mv, const float* __restrict__ wk_s2mv,
    const float* __restrict__ wk_m2s, const float* __restrict__ wk_s2s,
    const float* __restrict__ bk_mv, const float* __restrict__ bk_s,
    const float* __restrict__ wv_mv, const float* __restrict__ wv_s2mv,
    const float* __restrict__ wv_m2s, const float* __restrict__ wv_s2s,
    const float* __restrict__ bv_mv, const float* __restrict__ bv_s)
{
    __shared__ float xT[256 * 33];
    __shared__ float xsT[32 * 33];

    const int sel = blockIdx.y;
    const int ntok = (sel == 0) ? NQ_ : NKV_;
    const int ntiles = (B_ * ntok) / 32;
    const int tile = blockIdx.x;
    if (tile >= ntiles) return;

    const float* x_mv = (sel == 0) ? mv_q : mv_kv;
    const float* x_s  = (sel == 0) ? s_q  : s_kv;
    const float* w_mv    = (sel == 0) ? wq_mv  : (sel == 1) ? wk_mv  : wv_mv;
    const float* w_s2mv  = (sel == 0) ? wq_s2mv: (sel == 1) ? wk_s2mv: wv_s2mv;
    const float* w_mvs2s = (sel == 0) ? wq_m2s : (sel == 1) ? wk_m2s : wv_m2s;
    const float* w_s2s   = (sel == 0) ? wq_s2s : (sel == 1) ? wk_s2s : wv_s2s;
    const float* b_mv    = (sel == 0) ? bq_mv  : (sel == 1) ? bk_mv  : bv_mv;
    const float* b_s     = (sel == 0) ? bq_s   : (sel == 1) ? bk_s   : bv_s;
    float* out = (sel == 0) ? QB : (sel == 1) ? KB : VB;
    const int applyMetric = (sel == 1);

    const int tid = threadIdx.x, w = tid >> 5, lane = tid & 31;
    const int t0 = tile * 32;
    const int b = t0 / ntok, n0 = t0 % ntok;

    {
        const float4* src = (const float4*)(x_mv + (size_t)t0 * 256);
#pragma unroll
        for (int i = 0; i < 16; ++i) {
            int f4 = i * 128 + tid;
            int tok = f4 >> 6, feat4 = f4 & 63;
            float4 v = src[f4];
            xT[(feat4 * 4 + 0) * 33 + tok] = v.x;
            xT[(feat4 * 4 + 1) * 33 + tok] = v.y;
            xT[(feat4 * 4 + 2) * 33 + tok] = v.z;
            xT[(feat4 * 4 + 3) * 33 + tok] = v.w;
        }
        const float* ssrc = x_s + (size_t)t0 * 32;
#pragma unroll
        for (int i = 0; i < 8; ++i) {
            int idx = i * 128 + tid;
            int tok = idx >> 5, s = idx & 31;
            xsT[s * 33 + tok] = ssrc[tok * 32 + s];
        }
    }
    __syncthreads();

    for (int oc = 0; oc < 32; ++oc) {
        const int o = w * 32 + oc;
        const float* wr = w_mv + o * 80;
        float a0 = b_mv[o];
        const float* ws = w_s2mv + o * 32;
#pragma unroll
        for (int s = 0; s < 32; ++s) a0 += xsT[s * 33 + lane] * ws[s];

        const int head = o & 7, hid = o >> 3;
        float* op = out + ((size_t)(b * 8 + head) * ntok + (n0 + lane)) * D_ + hid * 16;
#pragma unroll
        for (int x = 0; x < 16; ++x) {
            float acc = (x == 0) ? a0 : 0.f;
            const int g = GRADEA[x];
#pragma unroll
            for (int i = 0; i < 16; ++i)
                acc += xT[(i * 16 + x) * 33 + lane] * wr[i * 5 + g];
            op[x] = applyMetric ? acc * METRICA[x] : acc;
        }
    }

    for (int oc = 0; oc < 64; ++oc) {
        const int o = w * 64 + oc;
        float y = b_s[o];
        const float* wm = w_mvs2s + o * 16;
#pragma unroll
        for (int i = 0; i < 16; ++i) y += xT[(i * 16) * 33 + lane] * wm[i];
        const float* ws = w_s2s + o * 32;
#pragma unroll
        for (int s = 0; s < 32; ++s) y += xsT[s * 33 + lane] * ws[s];
        const int head = o & 7, hid = o >> 3;
        out[((size_t)(b * 8 + head) * ntok + (n0 + lane)) * D_ + 256 + hid] = y;
    }
}

// ============================================================================
// repackQ: grid (8, 32), 256 thr.
// ============================================================================
#define STGS 292
__global__ void repackQ_kernel()
{
    extern __shared__ float ss[];
    const int qt = blockIdx.x, bh = blockIdx.y, tid = threadIdx.x;
    const float SCALE = 0.0589255650988789f;
    const float* src = QB + ((size_t)bh * NQ_ + qt * 128) * D_;
#pragma unroll
    for (int i = 0; i < 36; ++i) {
        int idx = i * 256 + tid, row = idx / 72, c4 = idx % 72;
        float4 v = *(const float4*)(src + (size_t)row * D_ + c4 * 4);
        float* d = ss + row * STGS + c4 * 4;
        d[0] = v.x; d[1] = v.y; d[2] = v.z; d[3] = v.w;
    }
    __syncthreads();
    uint32_t* dst = QFG + (size_t)(bh * 8 + qt) * 36864;
#pragma unroll
    for (int i = 0; i < 18; ++i) {
        int gidx = i * 256 + tid;
        int ms = gidx / 576, rem = gidx % 576, ks = rem >> 5, lane = rem & 31;
        int g = lane >> 2, t = lane & 3;
        int r0 = ms * 16 + g, c0 = ks * 16 + 2 * t;
        float v[8];
        v[0] = ss[r0 * STGS + c0] * SCALE;        v[1] = ss[r0 * STGS + c0 + 1] * SCALE;
        v[2] = ss[(r0+8) * STGS + c0] * SCALE;    v[3] = ss[(r0+8) * STGS + c0 + 1] * SCALE;
        v[4] = ss[r0 * STGS + c0 + 8] * SCALE;    v[5] = ss[r0 * STGS + c0 + 9] * SCALE;
        v[6] = ss[(r0+8) * STGS + c0 + 8] * SCALE;v[7] = ss[(r0+8) * STGS + c0 + 9] * SCALE;
        uint4 hi = { pk2b(v[0],v[1]), pk2b(v[2],v[3]), pk2b(v[4],v[5]), pk2b(v[6],v[7]) };
        uint4 lo = { pk2b(bf16res(v[0]),bf16res(v[1])), pk2b(bf16res(v[2]),bf16res(v[3])),
                     pk2b(bf16res(v[4]),bf16res(v[5])), pk2b(bf16res(v[6]),bf16res(v[7])) };
        *(uint4*)(dst + (size_t)gidx * 4)          = hi;
        *(uint4*)(dst + 18432 + (size_t)gidx * 4)  = lo;
    }
}

// ============================================================================
// repackKV: K hi+lo (R10 config); V hi+lo. grid (32, 32, 2), 256 thr.
// ============================================================================
__global__ void repackKV_kernel()
{
    extern __shared__ float ss[];
    const int kt = blockIdx.x, bh = blockIdx.y, zv = blockIdx.z, tid = threadIdx.x;
    const float* src = (zv ? VB : KB) + ((size_t)bh * NKV_ + kt * 64) * D_;
#pragma unroll
    for (int i = 0; i < 18; ++i) {
        int idx = i * 256 + tid, row = idx / 72, c4 = idx % 72;
        float4 v = *(const float4*)(src + (size_t)row * D_ + c4 * 4);
        float* d = ss + row * STGS + c4 * 4;
        d[0] = v.x; d[1] = v.y; d[2] = v.z; d[3] = v.w;
    }
    __syncthreads();
    uint32_t* dst = (zv ? VFG : KFG) + (size_t)(bh * 32 + kt) * 3 * 6144;
    if (!zv) {
#pragma unroll
        for (int i = 0; i < 18; ++i) {
            int e = i * 256 + tid;
            int c = e / 1536, rem = e % 1536;
            int n = rem / 192, rem2 = rem % 192, ksl = rem2 >> 5, lane = rem2 & 31;
            int g = lane >> 2, t = lane & 3;
            int key = n * 8 + g, d0 = c * 96 + ksl * 16 + 2 * t;
            float x0 = ss[key * STGS + d0],     x1 = ss[key * STGS + d0 + 1];
            float x2 = ss[key * STGS + d0 + 8], x3 = ss[key * STGS + d0 + 9];
            uint32_t* ch = dst + (size_t)c * 6144;
            int go = ((n * 6 + ksl) * 32 + lane) * 2;
            *(uint2*)(ch + go)        = make_uint2(pk2b(x0, x1), pk2b(x2, x3));
            *(uint2*)(ch + 3072 + go) = make_uint2(pk2b(bf16res(x0), bf16res(x1)),
                                                   pk2b(bf16res(x2), bf16res(x3)));
        }
    } else {
#pragma unroll
        for (int i = 0; i < 18; ++i) {
            int e = i * 256 + tid;
            int c = e / 1536, rem = e % 1536;
            int ntl = rem / 128, rem2 = rem % 128, ks = rem2 >> 5, lane = rem2 & 31;
            int g = lane >> 2, t = lane & 3;
            int key0 = ks * 16 + 2 * t, d = c * 96 + ntl * 8 + g;
            float x0 = ss[key0 * STGS + d],       x1 = ss[(key0+1) * STGS + d];
            float x2 = ss[(key0+8) * STGS + d],   x3 = ss[(key0+9) * STGS + d];
            uint32_t* ch = dst + (size_t)c * 6144;
            int go = ((ntl * 4 + ks) * 32 + lane) * 2;
            *(uint2*)(ch + go)        = make_uint2(pk2b(x0, x1), pk2b(x2, x3));
            *(uint2*)(ch + 3072 + go) = make_uint2(pk2b(bf16res(x0), bf16res(x1)),
                                                   pk2b(bf16res(x2), bf16res(x3)));
        }
    }
}

// ============================================================================
// attn8: register-resident FA2, split-bf16 — EXACT R10 config.
// ============================================================================
#define SM_BYTES (147456 + 3 * 24576 + 64)

__global__ __launch_bounds__(256, 1) void attn8_kernel()
{
    extern __shared__ uint32_t smu[];
    uint32_t* Qh = smu;
    uint32_t* Ql = smu + 18432;
    uint32_t* bufs[3] = { smu + 36864, smu + 43008, smu + 49152 };

    const int tid = threadIdx.x, bh = blockIdx.y, qt = blockIdx.x;
    const int w = tid >> 5, lane = tid & 31, g = lane >> 2, t = lane & 3;

    const uint32_t sb = smem_u32(smu);
    const uint32_t mbase = sb + (36864 + 3 * 6144) * 4;
    const uint32_t mbQ = mbase + 24;

    const uint32_t* KFb = KFG + (size_t)(bh * 32) * 3 * 6144;
    const uint32_t* VFb = VFG + (size_t)(bh * 32) * 3 * 6144;

    if (tid == 0) {
        MB_INIT(mbase + 0, 1); MB_INIT(mbase + 8, 1); MB_INIT(mbase + 16, 1);
        MB_INIT(mbQ, 1);
    }
    __syncthreads();
    if (tid == 0) {
        MB_EXPECT(mbQ, 147456u);
        bulkld(sb, QFG + (size_t)(bh * 8 + qt) * 36864, mbQ, 147456u);
#pragma unroll
        for (int c = 0; c < 3; ++c) {
            MB_EXPECT(mbase + 8 * c, 24576u);
            bulkld(sb + (36864 + c * 6144) * 4, KFb + c * 6144, mbase + 8 * c, 24576u);
        }
    }

    float O[3][12][4];
#pragma unroll
    for (int c = 0; c < 3; ++c)
#pragma unroll
        for (int n = 0; n < 12; ++n)
#pragma unroll
            for (int k = 0; k < 4; ++k) O[c][n][k] = 0.f;
    float mA = -1e30f, mB = -1e30f, lA = 0.f, lB = 0.f;

    MB_WAIT(mbQ, 0);

    for (int kt = 0; kt < 32; ++kt) {
        const uint32_t* VFt = VFb + (size_t)kt * 3 * 6144;
        const uint32_t* KFn = KFb + (size_t)(kt + 1) * 3 * 6144;

        float cS[8][4];
#pragma unroll
        for (int n = 0; n < 8; ++n)
#pragma unroll
            for (int k = 0; k < 4; ++k) cS[n][k] = 0.f;

#pragma unroll
        for (int c = 0; c < 3; ++c) {
            MB_WAIT(mbase + 8 * c, 0);
            const uint32_t* buf = bufs[c];
#pragma unroll
            for (int ksl = 0; ksl < 6; ++ksl) {
                const int ksg = c * 6 + ksl;
                uint4 Ah = *(const uint4*)(Qh + ((w * 18 + ksg) * 32 + lane) * 4);
                uint4 Al = *(const uint4*)(Ql + ((w * 18 + ksg) * 32 + lane) * 4);
#pragma unroll
                for (int n = 0; n < 8; ++n) {
                    uint2 bh2 = *(const uint2*)(buf + ((n * 6 + ksl) * 32 + lane) * 2);
                    uint2 bl2 = *(const uint2*)(buf + 3072 + ((n * 6 + ksl) * 32 + lane) * 2);
                    MMA16(cS[n], Ah.x, Ah.y, Ah.z, Ah.w, bh2.x, bh2.y);
                    MMA16(cS[n], Al.x, Al.y, Al.z, Al.w, bh2.x, bh2.y);
                    MMA16(cS[n], Ah.x, Ah.y, Ah.z, Ah.w, bl2.x, bl2.y);
                }
            }
            __syncthreads();
            if (tid == 0) {
                MB_EXPECT(mbase + 8 * c, 24576u);
                bulkld(sb + (36864 + c * 6144) * 4, VFt + c * 6144, mbase + 8 * c, 24576u);
            }
        }

        float mxA = -1e30f, mxB = -1e30f;
#pragma unroll
        for (int n = 0; n < 8; ++n) {
            mxA = fmaxf(mxA, fmaxf(cS[n][0], cS[n][1]));
            mxB = fmaxf(mxB, fmaxf(cS[n][2], cS[n][3]));
        }
        mxA = fmaxf(mxA, __shfl_xor_sync(0xffffffffu, mxA, 1));
        mxA = fmaxf(mxA, __shfl_xor_sync(0xffffffffu, mxA, 2));
        mxB = fmaxf(mxB, __shfl_xor_sync(0xffffffffu, mxB, 1));
        mxB = fmaxf(mxB, __shfl_xor_sync(0xffffffffu, mxB, 2));
        const float mnA = fmaxf(mA, mxA), mnB = fmaxf(mB, mxB);
        const float alA = __expf(mA - mnA), alB = __expf(mB - mnB);
        mA = mnA; mB = mnB;

        uint32_t PhT[8], PhB[8], PlT[8], PlB[8];
        float sA = 0.f, sB = 0.f;
#pragma unroll
        for (int n = 0; n < 8; ++n) {
            float e0 = __expf(cS[n][0] - mnA), e1 = __expf(cS[n][1] - mnA);
            float e2 = __expf(cS[n][2] - mnB), e3 = __expf(cS[n][3] - mnB);
            sA += e0 + e1; sB += e2 + e3;
            PhT[n] = pk2b(e0, e1); PhB[n] = pk2b(e2, e3);
            PlT[n] = pk2b(bf16res(e0), bf16res(e1));
            PlB[n] = pk2b(bf16res(e2), bf16res(e3));
        }
        sA += __shfl_xor_sync(0xffffffffu, sA, 1);
        sA += __shfl_xor_sync(0xffffffffu, sA, 2);
        sB += __shfl_xor_sync(0xffffffffu, sB, 1);
        sB += __shfl_xor_sync(0xffffffffu, sB, 2);
        lA = lA * alA + sA;
        lB = lB * alB + sB;
#pragma unroll
        for (int c = 0; c < 3; ++c)
#pragma unroll
            for (int n = 0; n < 12; ++n) {
                O[c][n][0] *= alA; O[c][n][1] *= alA;
                O[c][n][2] *= alB; O[c][n][3] *= alB;
            }

#pragma unroll
        for (int c = 0; c < 3; ++c) {
            MB_WAIT(mbase + 8 * c, 1);
            const uint32_t* buf = bufs[c];
#pragma unroll
            for (int ks = 0; ks < 4; ++ks) {
                uint32_t ah0 = PhT[2*ks], ah1 = PhB[2*ks], ah2 = PhT[2*ks+1], ah3 = PhB[2*ks+1];
                uint32_t al0 = PlT[2*ks], al1 = PlB[2*ks], al2 = PlT[2*ks+1], al3 = PlB[2*ks+1];
#pragma unroll
                for (int ntl = 0; ntl < 12; ++ntl) {
                    uint2 vh = *(const uint2*)(buf + ((ntl * 4 + ks) * 32 + lane) * 2);
                    uint2 vl = *(const uint2*)(buf + 3072 + ((ntl * 4 + ks) * 32 + lane) * 2);
                    MMA16(O[c][ntl], ah0, ah1, ah2, ah3, vh.x, vh.y);
                    MMA16(O[c][ntl], al0, al1, al2, al3, vh.x, vh.y);
                    MMA16(O[c][ntl], ah0, ah1, ah2, ah3, vl.x, vl.y);
                }
            }
            __syncthreads();
            if (kt < 31 && tid == 0) {
                MB_EXPECT(mbase + 8 * c, 24576u);
                bulkld(sb + (36864 + c * 6144) * 4, KFn + c * 6144, mbase + 8 * c, 24576u);
            }
        }
    }

    const float liA = 1.f / lA, liB = 1.f / lB;
    const int b = bh >> 3, hh = bh & 7;
    const int rA = qt * 128 + w * 16 + g, rB = rA + 8;
    float* oA = OB + (((size_t)(b * NQ_ + rA)) * 8 + hh) * D_;
    float* oB = OB + (((size_t)(b * NQ_ + rB)) * 8 + hh) * D_;
#pragma unroll
    for (int c = 0; c < 3; ++c)
#pragma unroll
        for (int n = 0; n < 12; ++n) {
            int d = c * 96 + n * 8 + 2 * t;
            *(float2*)(oA + d) = make_float2(O[c][n][0] * liA, O[c][n][1] * liA);
            *(float2*)(oB + d) = make_float2(O[c][n][2] * liB, O[c][n][3] * liB);
        }
}

// ============================================================================
// outproj2: 8-token tiles, 256 threads. grid = 512.
// ============================================================================
#define OP_SMEM (2304 * 9 * 4 + 128 * 4)

__global__ void outproj2_kernel(const float* __restrict__ wo_mv, const float* __restrict__ wo_s2mv,
                                const float* __restrict__ wo_mvs2s, const float* __restrict__ wo_s2s,
                                const float* __restrict__ bo_mv, const float* __restrict__ bo_s,
                                float* __restrict__ d_out)
{
    extern __shared__ float xT[];           // [2304][9]
    float* a0sm = xT + 2304 * 9;            // [tok8][o16]
    const int blk = blockIdx.x, tid = threadIdx.x;

    {
        const float4* src = (const float4*)(OB + (size_t)blk * 8 * 2304);
#pragma unroll
        for (int i = 0; i < 18; ++i) {
            int idx = i * 256 + tid;
            int tok = idx / 576, f4 = idx % 576;
            float4 v = src[(size_t)tok * 576 + f4];
            xT[(f4 * 4 + 0) * 9 + tok] = v.x;
            xT[(f4 * 4 + 1) * 9 + tok] = v.y;
            xT[(f4 * 4 + 2) * 9 + tok] = v.z;
            xT[(f4 * 4 + 3) * 9 + tok] = v.w;
        }
    }
    __syncthreads();

    {
        const int tok = tid >> 5, o = (tid >> 1) & 15, part = tid & 1;
        float a = 0.f;
        const float* ws = wo_s2mv + o * 256 + part * 128;
#pragma unroll
        for (int s = 0; s < 128; ++s) {
            int s2 = part * 128 + s;
            int feat = (s2 >> 5) * 288 + 256 + (s2 & 31);
            a += xT[feat * 9 + tok] * ws[s];
        }
        a += __shfl_xor_sync(0xffffffffu, a, 1);
        if (part == 0) a0sm[tok * 16 + o] = a + bo_mv[o];
    }
    __syncthreads();

    const int og = tid >> 3, tok = tid & 7;
    const int tglob = blk * 8 + tok;

#pragma unroll
    for (int j = 0; j < 8; ++j) {
        const int outIdx = j * 32 + og;
        const int o = outIdx >> 4, x = outIdx & 15;
        const int gg = GRADE_RT[x];
        const float* wp = wo_mv + (size_t)o * 640 + gg;
        float y = (x == 0) ? a0sm[tok * 16 + o] : 0.f;
#pragma unroll 16
        for (int i = 0; i < 128; ++i) {
            int feat = (i >> 4) * 288 + (i & 15) * 16 + x;
            y += xT[feat * 9 + tok] * wp[i * 5];
        }
        d_out[(size_t)tglob * 256 + outIdx] = y;
    }
    {
        const int s = og;
        float y = bo_s[s];
        const float* wm = wo_mvs2s + s * 128;
#pragma unroll 16
        for (int i = 0; i < 128; ++i) {
            int feat = (i >> 4) * 288 + (i & 15) * 16;
            y += xT[feat * 9 + tok] * wm[i];
        }
        const float* ws = wo_s2s + s * 256;
#pragma unroll 16
        for (int s2 = 0; s2 < 256; ++s2) {
            int feat = (s2 >> 5) * 288 + 256 + (s2 & 31);
            y += xT[feat * 9 + tok] * ws[s2];
        }
        d_out[(size_t)B_ * NQ_ * 256 + (size_t)tglob * 32 + s] = y;
    }
}

extern "C" void kernel_launch(void* const* d_in, const int* in_sizes, int n_in,
                              void* d_out, int out_size)
{
    (void)in_sizes; (void)n_in; (void)out_size;
    const float* mv_kv = (const float*)d_in[0];
    const float* mv_q  = (const float*)d_in[1];
    const float* s_kv  = (const float*)d_in[2];
    const float* s_q   = (const float*)d_in[3];
    const float* wq_mv = (const float*)d_in[4],  *wq_s2mv = (const float*)d_in[5];
    const float* wq_m2s = (const float*)d_in[6], *wq_s2s = (const float*)d_in[7];
    const float* bq_mv = (const float*)d_in[8],  *bq_s = (const float*)d_in[9];
    const float* wk_mv = (const float*)d_in[10], *wk_s2mv = (const float*)d_in[11];
    const float* wk_m2s = (const float*)d_in[12],*wk_s2s = (const float*)d_in[13];
    const float* bk_mv = (const float*)d_in[14], *bk_s = (const float*)d_in[15];
    const float* wv_mv = (const float*)d_in[16], *wv_s2mv = (const float*)d_in[17];
    const float* wv_m2s = (const float*)d_in[18],*wv_s2s = (const float*)d_in[19];
    const float* bv_mv = (const float*)d_in[20], *bv_s = (const float*)d_in[21];
    const float* wo_mv = (const float*)d_in[22], *wo_s2mv = (const float*)d_in[23];
    const float* wo_m2s = (const float*)d_in[24],*wo_s2s = (const float*)d_in[25];
    const float* bo_mv = (const float*)d_in[26], *bo_s = (const float*)d_in[27];

    const int stageQ = 128 * STGS * sizeof(float);
    const int stageKV = 64 * STGS * sizeof(float);
    cudaFuncSetAttribute(repackQ_kernel, cudaFuncAttributeMaxDynamicSharedMemorySize, stageQ);
    cudaFuncSetAttribute(repackKV_kernel, cudaFuncAttributeMaxDynamicSharedMemorySize, stageKV);
    cudaFuncSetAttribute(attn8_kernel, cudaFuncAttributeMaxDynamicSharedMemorySize, SM_BYTES);
    cudaFuncSetAttribute(outproj2_kernel, cudaFuncAttributeMaxDynamicSharedMemorySize, OP_SMEM);

    proj2_kernel<<<dim3(256, 3), 128>>>(
        mv_q, s_q, mv_kv, s_kv,
        wq_mv, wq_s2mv, wq_m2s, wq_s2s, bq_mv, bq_s,
        wk_mv, wk_s2mv, wk_m2s, wk_s2s, bk_mv, bk_s,
        wv_mv, wv_s2mv, wv_m2s, wv_s2s, bv_mv, bv_s);
    repackQ_kernel<<<dim3(8, 32), 256, stageQ>>>();
    repackKV_kernel<<<dim3(32, 32, 2), 256, stageKV>>>();
    attn8_kernel<<<dim3(8, 32), 256, SM_BYTES>>>();
    outproj2_kernel<<<512, 256, OP_SMEM>>>(wo_mv, wo_s2mv, wo_m2s, wo_s2s, bo_mv, bo_s,
                                           (float*)d_out);
}